// round 6
// baseline (speedup 1.0000x reference)
#include <cuda_runtime.h>
#include <math.h>

#define NMAX 50048
#define EMAX 800000
#define SCAN_B 256

// ---------------- scratch (device globals) ----------------
__device__ float g_h[NMAX * 128];      // x @ W_gat
__device__ float g_h2[NMAX * 128];     // out1 @ W_gcn
__device__ float g_asrc[NMAX * 4];
__device__ float g_adst[NMAX * 4];
__device__ float g_out1[NMAX * 128];
__device__ float g_out2[NMAX * 128];
__device__ float g_gate[NMAX];
__device__ float g_dinv[NMAX];
__device__ int   g_cnt[NMAX];
__device__ int   g_offs[NMAX + 1];
__device__ int   g_cursor[NMAX];
__device__ int   g_csr[EMAX];
__device__ float4 g_w4[EMAX];          // per-edge GAT exp weights (4 heads)
__device__ float g_wgcn[EMAX];         // per-edge GCN norm
__device__ int   g_bsum[(NMAX + SCAN_B - 1) / SCAN_B];
__device__ int   g_boff[(NMAX + SCAN_B - 1) / SCAN_B];
__device__ int   g_gstart[64];
__device__ int   g_gend[64];
__device__ float g_gmax[64];
__device__ float g_gsum[64];
__device__ float g_gacc[64 * 128];

// ---------------- helpers ----------------
__device__ __forceinline__ float lrelu(float v) { return v > 0.f ? v : 0.2f * v; }
__device__ __forceinline__ float elu_f(float v) { return v > 0.f ? v : (__expf(v) - 1.f); }
__device__ __forceinline__ float getc(float4 v, int i) {
    return i == 0 ? v.x : i == 1 ? v.y : i == 2 ? v.z : v.w;
}
__device__ __forceinline__ void atomicMaxF(float* a, float v) {
    if (v >= 0.f) atomicMax((int*)a, __float_as_int(v));
    else          atomicMin((unsigned int*)a, __float_as_uint(v));
}
__device__ __forceinline__ void ffma2(unsigned long long& d, unsigned long long a,
                                      unsigned long long b) {
    asm("fma.rn.f32x2 %0, %1, %2, %0;" : "+l"(d) : "l"(a), "l"(b));
}
__device__ __forceinline__ unsigned long long dup2(float v) {
    unsigned long long r;
    asm("mov.b64 %0, {%1, %1};" : "=l"(r) : "f"(v));
    return r;
}

// ---------------- init (+ graph bounds fused) ----------------
__global__ void init_kernel(int* cnt, int* gs, int* ge, float* gmax_, float* gsum,
                            float* gacc, const int* __restrict__ batch, int N) {
    int i = blockIdx.x * blockDim.x + threadIdx.x;
    if (i < N) {
        cnt[i] = 0;
        int b = batch[i];
        if (i == 0 || batch[i - 1] != b) gs[b] = i;
        if (i == N - 1 || batch[i + 1] != b) ge[b] = i + 1;
    }
    if (i < 64) { gmax_[i] = -3.4e38f; gsum[i] = 0.f; }
    if (i < 64 * 128) gacc[i] = 0.f;
}

// ---------------- CSR: histogram ----------------
__global__ void hist_kernel(const int* __restrict__ ei, int E, int* cnt) {
    int e = blockIdx.x * blockDim.x + threadIdx.x;
    if (e >= E) return;
    atomicAdd(cnt + ei[E + e], 1);
}

__global__ __launch_bounds__(SCAN_B) void blocksum_kernel(const int* __restrict__ cnt,
                                                          int* bsum, int N) {
    __shared__ int sh[SCAN_B];
    int i = blockIdx.x * SCAN_B + threadIdx.x;
    sh[threadIdx.x] = (i < N) ? cnt[i] : 0;
    __syncthreads();
    #pragma unroll
    for (int o = SCAN_B / 2; o; o >>= 1) {
        if (threadIdx.x < o) sh[threadIdx.x] += sh[threadIdx.x + o];
        __syncthreads();
    }
    if (threadIdx.x == 0) bsum[blockIdx.x] = sh[0];
}

// ---------------- GEMM: C[N,128] = A[N,128] @ W[128,128] (+ optional attn epilogue) ----------------
template <bool ATTN>
__global__ __launch_bounds__(256) void gemm128_kernel(const float* __restrict__ A,
                                                      const float* __restrict__ W,
                                                      float* __restrict__ C,
                                                      const float* __restrict__ att_src,
                                                      const float* __restrict__ att_dst,
                                                      float* __restrict__ asrc,
                                                      float* __restrict__ adst, int N) {
    __shared__ float Ws[32 * 128];
    int t  = threadIdx.x;
    int cg = t & 7;
    int rq = t >> 3;
    int row0 = blockIdx.x * 128 + rq * 4;

    unsigned long long acc[4][8];
    #pragma unroll
    for (int j = 0; j < 4; j++)
        #pragma unroll
        for (int i = 0; i < 8; i++) acc[j][i] = 0ull;

    #pragma unroll
    for (int kk = 0; kk < 128; kk += 32) {
        __syncthreads();
        #pragma unroll
        for (int i = t; i < 1024; i += 256)
            ((float4*)Ws)[i] = ((const float4*)W)[kk * 32 + i];
        __syncthreads();

        #pragma unroll
        for (int k4 = 0; k4 < 8; k4++) {
            float4 a[4];
            #pragma unroll
            for (int j = 0; j < 4; j++) {
                int row = row0 + j;
                a[j] = (row < N) ? ((const float4*)A)[row * 32 + (kk >> 2) + k4]
                                 : make_float4(0.f, 0.f, 0.f, 0.f);
            }
            #pragma unroll
            for (int u = 0; u < 4; u++) {
                const float* wr = Ws + (k4 * 4 + u) * 128 + cg * 16;
                ulonglong2 w0 = *(const ulonglong2*)(wr);
                ulonglong2 w1 = *(const ulonglong2*)(wr + 4);
                ulonglong2 w2 = *(const ulonglong2*)(wr + 8);
                ulonglong2 w3 = *(const ulonglong2*)(wr + 12);
                #pragma unroll
                for (int j = 0; j < 4; j++) {
                    unsigned long long av2 = dup2(getc(a[j], u));
                    ffma2(acc[j][0], av2, w0.x); ffma2(acc[j][1], av2, w0.y);
                    ffma2(acc[j][2], av2, w1.x); ffma2(acc[j][3], av2, w1.y);
                    ffma2(acc[j][4], av2, w2.x); ffma2(acc[j][5], av2, w2.y);
                    ffma2(acc[j][6], av2, w3.x); ffma2(acc[j][7], av2, w3.y);
                }
            }
        }
    }

    float cf[4][16];
    #pragma unroll
    for (int j = 0; j < 4; j++)
        #pragma unroll
        for (int m = 0; m < 4; m++) {
            float2 lo = *(float2*)&acc[j][2 * m];
            float2 hi = *(float2*)&acc[j][2 * m + 1];
            cf[j][m * 4 + 0] = lo.x; cf[j][m * 4 + 1] = lo.y;
            cf[j][m * 4 + 2] = hi.x; cf[j][m * 4 + 3] = hi.y;
        }

    #pragma unroll
    for (int j = 0; j < 4; j++) {
        int row = row0 + j;
        if (row < N) {
            float4* cp = (float4*)(C + row * 128 + cg * 16);
            #pragma unroll
            for (int m = 0; m < 4; m++)
                cp[m] = make_float4(cf[j][m * 4], cf[j][m * 4 + 1],
                                    cf[j][m * 4 + 2], cf[j][m * 4 + 3]);
        }
    }

    if (ATTN) {
        int hg = cg >> 1;
        const float* as_p = att_src + hg * 32 + (cg & 1) * 16;
        const float* ad_p = att_dst + hg * 32 + (cg & 1) * 16;
        float av[16], dv[16];
        #pragma unroll
        for (int k = 0; k < 16; k++) { av[k] = as_p[k]; dv[k] = ad_p[k]; }
        #pragma unroll
        for (int j = 0; j < 4; j++) {
            float ps = 0.f, pd = 0.f;
            #pragma unroll
            for (int k = 0; k < 16; k++) { ps += cf[j][k] * av[k]; pd += cf[j][k] * dv[k]; }
            ps += __shfl_xor_sync(0xffffffffu, ps, 1);
            pd += __shfl_xor_sync(0xffffffffu, pd, 1);
            int row = row0 + j;
            if (!(cg & 1) && row < N) {
                asrc[row * 4 + hg] = ps;
                adst[row * 4 + hg] = pd;
            }
        }
    }
}

__global__ __launch_bounds__(256) void bscan_kernel(const int* __restrict__ bsum,
                                                    int* boff, int NB) {
    __shared__ int sh[256];
    int t = threadIdx.x;
    sh[t] = (t < NB) ? bsum[t] : 0;
    __syncthreads();
    #pragma unroll
    for (int o = 1; o < 256; o <<= 1) {
        int v = (t >= o) ? sh[t - o] : 0;
        __syncthreads();
        sh[t] += v;
        __syncthreads();
    }
    if (t < NB) boff[t] = (t == 0) ? 0 : sh[t - 1];
}

// scanfin also emits dinv (deg = cnt + 1 self loop)
__global__ __launch_bounds__(SCAN_B) void scanfin_kernel(const int* __restrict__ cnt,
                                                         const int* __restrict__ boff,
                                                         int* offs, int* cursor,
                                                         float* dinv, int N, int E) {
    __shared__ int sh[SCAN_B];
    int t = threadIdx.x;
    int i = blockIdx.x * SCAN_B + t;
    int v = (i < N) ? cnt[i] : 0;
    sh[t] = v;
    __syncthreads();
    #pragma unroll
    for (int o = 1; o < SCAN_B; o <<= 1) {
        int u = (t >= o) ? sh[t - o] : 0;
        __syncthreads();
        sh[t] += u;
        __syncthreads();
    }
    if (i < N) {
        int off = boff[blockIdx.x] + sh[t] - v;
        offs[i] = off;
        cursor[i] = off;
        dinv[i] = rsqrtf((float)(v + 1));
    }
    if (i == 0) offs[N] = E;
}

// ---------------- scatter + per-edge weight precompute ----------------
__global__ void scatter_kernel(const int* __restrict__ ei, int E, int* cursor, int* csr,
                               const float* __restrict__ asrc,
                               const float* __restrict__ adst,
                               const float* __restrict__ dinv,
                               float4* __restrict__ w4, float* __restrict__ wgcn) {
    int e = blockIdx.x * blockDim.x + threadIdx.x;
    if (e >= E) return;
    int s = ei[e];
    int d = ei[E + e];
    int pos = atomicAdd(cursor + d, 1);
    csr[pos] = s;
    float4 as = *(const float4*)(asrc + s * 4);
    float4 ad = *(const float4*)(adst + d * 4);
    float4 w;
    w.x = __expf(lrelu(as.x + ad.x));
    w.y = __expf(lrelu(as.y + ad.y));
    w.z = __expf(lrelu(as.z + ad.z));
    w.w = __expf(lrelu(as.w + ad.w));
    w4[pos] = w;
    wgcn[pos] = dinv[s] * dinv[d];
}

// ---------------- GAT aggregation: warp/node, precomputed weights ----------------
__global__ __launch_bounds__(256) void gat_agg_kernel(const int* __restrict__ csr,
                                                      const int* __restrict__ offs,
                                                      const float* __restrict__ h,
                                                      const float* __restrict__ w4f,
                                                      const float* __restrict__ asrc,
                                                      const float* __restrict__ adst,
                                                      const float* __restrict__ b_gat,
                                                      const float* __restrict__ bn1w,
                                                      const float* __restrict__ bn1b,
                                                      float* __restrict__ out1, int N) {
    int n = (blockIdx.x * 256 + threadIdx.x) >> 5;
    if (n >= N) return;
    int lane = threadIdx.x & 31;
    int hd  = lane >> 3;
    int sub = lane & 7;
    int grp = lane & 24;
    int beg = offs[n], end = offs[n + 1];

    float wself = __expf(lrelu(__ldg(asrc + n * 4 + hd) + __ldg(adst + n * 4 + hd)));
    float4 hv = *(const float4*)(h + n * 128 + lane * 4);
    float4 acc = make_float4(hv.x * wself, hv.y * wself, hv.z * wself, hv.w * wself);

    // prefetch first chunk: (s, w) streamed, coalesced
    int s_nxt = 0; float w_nxt = 0.f;
    {
        int e = beg + sub;
        if (e < end) {
            s_nxt = __ldg(csr + e);
            w_nxt = __ldg(w4f + e * 4 + hd);
        }
    }
    float wpart = w_nxt;

    for (int c0 = beg; c0 < end; c0 += 8) {
        int s_cur = s_nxt; float w_cur = w_nxt;
        int e = c0 + 8 + sub;
        s_nxt = 0; w_nxt = 0.f;
        if (e < end) {
            s_nxt = __ldg(csr + e);
            w_nxt = __ldg(w4f + e * 4 + hd);
        }
        wpart += w_nxt;
        #pragma unroll
        for (int i = 0; i < 8; i++) {
            int   si = __shfl_sync(0xffffffffu, s_cur, i);
            float a  = __shfl_sync(0xffffffffu, w_cur, grp + i);
            float4 g = *(const float4*)(h + si * 128 + lane * 4);
            acc.x += g.x * a; acc.y += g.y * a;
            acc.z += g.z * a; acc.w += g.w * a;
        }
    }

    #pragma unroll
    for (int o = 1; o < 8; o <<= 1) wpart += __shfl_xor_sync(0xffffffffu, wpart, o);
    float inv = 1.f / (wpart + wself + 1e-16f);

    int c = lane * 4;
    float4 bb = *(const float4*)(b_gat + c);
    float4 w1 = *(const float4*)(bn1w + c);
    float4 b1 = *(const float4*)(bn1b + c);
    float4 v;
    v.x = elu_f(acc.x * inv + bb.x) * w1.x + b1.x;
    v.y = elu_f(acc.y * inv + bb.y) * w1.y + b1.y;
    v.z = elu_f(acc.z * inv + bb.z) * w1.z + b1.z;
    v.w = elu_f(acc.w * inv + bb.w) * w1.w + b1.w;
    *(float4*)(out1 + n * 128 + c) = v;
}

// ---------------- GCN aggregation + gate + graph-max ----------------
__global__ __launch_bounds__(256) void gcn_agg_kernel(const int* __restrict__ csr,
                                                      const int* __restrict__ offs,
                                                      const float* __restrict__ h2,
                                                      const float* __restrict__ wgcn,
                                                      const float* __restrict__ dinv,
                                                      const float* __restrict__ b_gcn,
                                                      const float* __restrict__ bn2w,
                                                      const float* __restrict__ bn2b,
                                                      const float* __restrict__ W_gate,
                                                      const float* __restrict__ b_gate,
                                                      const int* __restrict__ batch,
                                                      float* __restrict__ out2,
                                                      float* __restrict__ gate,
                                                      float* gmax_, int N) {
    int n = (blockIdx.x * 256 + threadIdx.x) >> 5;
    if (n >= N) return;
    int lane = threadIdx.x & 31;
    int sub = lane & 7;
    int beg = offs[n], end = offs[n + 1];
    float dn = __ldg(dinv + n);

    float fs = dn * dn;
    float4 hv = *(const float4*)(h2 + n * 128 + lane * 4);
    float4 acc = make_float4(hv.x * fs, hv.y * fs, hv.z * fs, hv.w * fs);

    int s_nxt = 0; float f_nxt = 0.f;
    {
        int e = beg + sub;
        if (e < end) {
            s_nxt = __ldg(csr + e);
            f_nxt = __ldg(wgcn + e);
        }
    }

    for (int c0 = beg; c0 < end; c0 += 8) {
        int s_cur = s_nxt; float f_cur = f_nxt;
        int e = c0 + 8 + sub;
        s_nxt = 0; f_nxt = 0.f;
        if (e < end) {
            s_nxt = __ldg(csr + e);
            f_nxt = __ldg(wgcn + e);
        }
        #pragma unroll
        for (int i = 0; i < 8; i++) {
            int   si = __shfl_sync(0xffffffffu, s_cur, i);
            float a  = __shfl_sync(0xffffffffu, f_cur, i);
            float4 g = *(const float4*)(h2 + si * 128 + lane * 4);
            acc.x += g.x * a; acc.y += g.y * a;
            acc.z += g.z * a; acc.w += g.w * a;
        }
    }

    int c = lane * 4;
    float4 bb = *(const float4*)(b_gcn + c);
    float4 w2 = *(const float4*)(bn2w + c);
    float4 b2 = *(const float4*)(bn2b + c);
    float4 v;
    v.x = elu_f(acc.x + bb.x) * w2.x + b2.x;
    v.y = elu_f(acc.y + bb.y) * w2.y + b2.y;
    v.z = elu_f(acc.z + bb.z) * w2.z + b2.z;
    v.w = elu_f(acc.w + bb.w) * w2.w + b2.w;
    *(float4*)(out2 + n * 128 + c) = v;

    float4 wg = *(const float4*)(W_gate + c);
    float p = v.x * wg.x + v.y * wg.y + v.z * wg.z + v.w * wg.w;
    #pragma unroll
    for (int o = 16; o; o >>= 1) p += __shfl_xor_sync(0xffffffffu, p, o);
    if (lane == 0) {
        float gv = p + b_gate[0];
        gate[n] = gv;
        atomicMaxF(gmax_ + batch[n], gv);
    }
}

// ---------------- pooling accumulate: warp per node, atomics into 64x128 ----------------
__global__ __launch_bounds__(256) void poolacc_kernel(const float* __restrict__ out2,
                                                      const float* __restrict__ gate,
                                                      const float* __restrict__ gmax_,
                                                      const int* __restrict__ batch,
                                                      float* gsum, float* gacc, int N) {
    int n = (blockIdx.x * 256 + threadIdx.x) >> 5;
    if (n >= N) return;
    int lane = threadIdx.x & 31;
    int b = __ldg(batch + n);
    float wv = 0.f;
    if (lane == 0) wv = __expf(gate[n] - gmax_[b]);
    wv = __shfl_sync(0xffffffffu, wv, 0);
    float4 v = *(const float4*)(out2 + n * 128 + lane * 4);
    atomicAdd((float4*)(gacc + b * 128 + lane * 4),
              make_float4(v.x * wv, v.y * wv, v.z * wv, v.w * wv));
    if (lane == 0) atomicAdd(gsum + b, wv);
}

// ---------------- final ----------------
__global__ __launch_bounds__(128) void final_kernel(const float* __restrict__ gacc,
                                                    const float* __restrict__ gsum,
                                                    const float* __restrict__ W_fc,
                                                    const float* __restrict__ b_fc,
                                                    float* out) {
    int g = blockIdx.x;
    int c = threadIdx.x;
    float v = gacc[g * 128 + c] / (gsum[g] + 1e-16f) * W_fc[c];
    #pragma unroll
    for (int o = 16; o; o >>= 1) v += __shfl_xor_sync(0xffffffffu, v, o);
    __shared__ float sr[4];
    if ((c & 31) == 0) sr[c >> 5] = v;
    __syncthreads();
    if (c == 0) out[g] = sr[0] + sr[1] + sr[2] + sr[3] + b_fc[0];
}

// ---------------- launch ----------------
extern "C" void kernel_launch(void* const* d_in, const int* in_sizes, int n_in,
                              void* d_out, int out_size) {
    const float* x       = (const float*)d_in[0];
    const int*   ei      = (const int*)d_in[1];
    const int*   batch   = (const int*)d_in[2];
    const float* W_gat   = (const float*)d_in[3];
    const float* att_src = (const float*)d_in[4];
    const float* att_dst = (const float*)d_in[5];
    const float* b_gat   = (const float*)d_in[6];
    const float* bn1w    = (const float*)d_in[7];
    const float* bn1b    = (const float*)d_in[8];
    const float* W_gcn   = (const float*)d_in[9];
    const float* b_gcn   = (const float*)d_in[10];
    const float* bn2w    = (const float*)d_in[11];
    const float* bn2b    = (const float*)d_in[12];
    const float* W_gate  = (const float*)d_in[13];
    const float* b_gate  = (const float*)d_in[14];
    const float* W_fc    = (const float*)d_in[15];
    const float* b_fc    = (const float*)d_in[16];
    float* out = (float*)d_out;

    int N = in_sizes[0] / 128;
    int E = in_sizes[1] / 2;
    int NB = (N + SCAN_B - 1) / SCAN_B;

    float *p_h, *p_h2, *p_asrc, *p_adst, *p_out1, *p_out2, *p_gate, *p_dinv;
    float *p_gmax, *p_gsum, *p_gacc, *p_wgcn;
    float4 *p_w4;
    int *p_cnt, *p_offs, *p_cursor, *p_csr, *p_bsum, *p_boff, *p_gs, *p_ge;
    cudaGetSymbolAddress((void**)&p_h,     g_h);
    cudaGetSymbolAddress((void**)&p_h2,    g_h2);
    cudaGetSymbolAddress((void**)&p_asrc,  g_asrc);
    cudaGetSymbolAddress((void**)&p_adst,  g_adst);
    cudaGetSymbolAddress((void**)&p_out1,  g_out1);
    cudaGetSymbolAddress((void**)&p_out2,  g_out2);
    cudaGetSymbolAddress((void**)&p_gate,  g_gate);
    cudaGetSymbolAddress((void**)&p_dinv,  g_dinv);
    cudaGetSymbolAddress((void**)&p_cnt,   g_cnt);
    cudaGetSymbolAddress((void**)&p_offs,  g_offs);
    cudaGetSymbolAddress((void**)&p_cursor,g_cursor);
    cudaGetSymbolAddress((void**)&p_csr,   g_csr);
    cudaGetSymbolAddress((void**)&p_w4,    g_w4);
    cudaGetSymbolAddress((void**)&p_wgcn,  g_wgcn);
    cudaGetSymbolAddress((void**)&p_bsum,  g_bsum);
    cudaGetSymbolAddress((void**)&p_boff,  g_boff);
    cudaGetSymbolAddress((void**)&p_gs,    g_gstart);
    cudaGetSymbolAddress((void**)&p_ge,    g_gend);
    cudaGetSymbolAddress((void**)&p_gmax,  g_gmax);
    cudaGetSymbolAddress((void**)&p_gsum,  g_gsum);
    cudaGetSymbolAddress((void**)&p_gacc,  g_gacc);

    // launch index 3 = gemm1 (ncu capture slot)
    init_kernel<<<(N + 255) / 256, 256>>>(p_cnt, p_gs, p_ge, p_gmax, p_gsum, p_gacc,
                                          batch, N);                              // 0
    hist_kernel<<<(E + 255) / 256, 256>>>(ei, E, p_cnt);                          // 1
    blocksum_kernel<<<NB, SCAN_B>>>(p_cnt, p_bsum, N);                            // 2
    gemm128_kernel<true><<<(N + 127) / 128, 256>>>(x, W_gat, p_h, att_src, att_dst,
                                                   p_asrc, p_adst, N);            // 3
    bscan_kernel<<<1, 256>>>(p_bsum, p_boff, NB);                                 // 4
    scanfin_kernel<<<NB, SCAN_B>>>(p_cnt, p_boff, p_offs, p_cursor, p_dinv, N, E);// 5
    scatter_kernel<<<(E + 255) / 256, 256>>>(ei, E, p_cursor, p_csr,
                                             p_asrc, p_adst, p_dinv, p_w4, p_wgcn);// 6
    gat_agg_kernel<<<(N * 32 + 255) / 256, 256>>>(p_csr, p_offs, p_h, (const float*)p_w4,
                                                  p_asrc, p_adst, b_gat, bn1w, bn1b,
                                                  p_out1, N);                     // 7
    gemm128_kernel<false><<<(N + 127) / 128, 256>>>(p_out1, W_gcn, p_h2,
                                                    nullptr, nullptr, nullptr, nullptr, N); // 8
    gcn_agg_kernel<<<(N * 32 + 255) / 256, 256>>>(p_csr, p_offs, p_h2, p_wgcn, p_dinv,
                                                  b_gcn, bn2w, bn2b, W_gate, b_gate,
                                                  batch, p_out2, p_gate, p_gmax, N); // 9
    poolacc_kernel<<<(N * 32 + 255) / 256, 256>>>(p_out2, p_gate, p_gmax, batch,
                                                  p_gsum, p_gacc, N);             // 10
    final_kernel<<<64, 128>>>(p_gacc, p_gsum, W_fc, b_fc, out);                   // 11
}

// round 7
// speedup vs baseline: 1.7563x; 1.7563x over previous
#include <cuda_runtime.h>
#include <math.h>

#define NMAX 50048
#define EMAX 800000
#define SCAN_B 256

// ---------------- scratch (device globals) ----------------
__device__ float g_h[NMAX * 128];      // x @ W_gat
__device__ float g_h2[NMAX * 128];     // out1 @ W_gcn
__device__ float g_asrc[NMAX * 4];
__device__ float g_adst[NMAX * 4];
__device__ float g_out1[NMAX * 128];
__device__ float g_out2[NMAX * 128];
__device__ float g_gate[NMAX];
__device__ float g_dinv[NMAX];
__device__ int   g_cnt[NMAX];
__device__ int   g_offs[NMAX + 1];
__device__ int   g_cursor[NMAX];
__device__ int   g_csr[EMAX];
__device__ int   g_bsum[(NMAX + SCAN_B - 1) / SCAN_B];
__device__ int   g_boff[(NMAX + SCAN_B - 1) / SCAN_B];
__device__ int   g_gstart[64];
__device__ int   g_gend[64];
// packed tf32 hi/lo weights: [slab16][col128][kq4] float2 (pair = k, k+4)
__device__ float2 g_wb1[8192];
__device__ float2 g_ws1[8192];
__device__ float2 g_wb2[8192];
__device__ float2 g_ws2[8192];

// ---------------- helpers ----------------
__device__ __forceinline__ float lrelu(float v) { return v > 0.f ? v : 0.2f * v; }
__device__ __forceinline__ float elu_f(float v) { return v > 0.f ? v : (__expf(v) - 1.f); }
__device__ __forceinline__ float tf32r(float x) {
    float r;
    asm("cvt.rna.tf32.f32 %0, %1;" : "=f"(r) : "f"(x));
    return r;
}
__device__ __forceinline__ void mma_tf32(float* d, const unsigned* a, unsigned b0, unsigned b1) {
    asm("mma.sync.aligned.m16n8k8.row.col.f32.tf32.tf32.f32 "
        "{%0,%1,%2,%3},{%4,%5,%6,%7},{%8,%9},{%0,%1,%2,%3};"
        : "+f"(d[0]), "+f"(d[1]), "+f"(d[2]), "+f"(d[3])
        : "r"(a[0]), "r"(a[1]), "r"(a[2]), "r"(a[3]), "r"(b0), "r"(b1));
}

// ---------------- init ----------------
__global__ void init_kernel(int* cnt, int* gs, int* ge, int N) {
    int i = blockIdx.x * blockDim.x + threadIdx.x;
    if (i < N) cnt[i] = 0;
    if (i < 64) { gs[i] = 0; ge[i] = 0; }
}

// ---------------- graph boundaries (batch sorted) ----------------
__global__ void bounds_kernel(const int* __restrict__ batch, int* gs, int* ge, int N) {
    int n = blockIdx.x * blockDim.x + threadIdx.x;
    if (n >= N) return;
    int b = batch[n];
    if (n == 0 || batch[n - 1] != b) gs[b] = n;
    if (n == N - 1 || batch[n + 1] != b) ge[b] = n + 1;
}

// ---------------- pack W into fragment-ordered tf32 hi/lo ----------------
__global__ void wpack_kernel(const float* __restrict__ W, float2* Wb, float2* Ws) {
    int t = blockIdx.x * blockDim.x + threadIdx.x;
    if (t >= 16 * 128 * 4) return;
    int kq   = t & 3;
    int col  = (t >> 2) & 127;
    int slab = t >> 9;
    int k0 = slab * 8 + kq;
    float v0 = W[k0 * 128 + col];
    float v1 = W[(k0 + 4) * 128 + col];
    float b0 = tf32r(v0), b1 = tf32r(v1);
    Wb[t] = make_float2(b0, b1);
    Ws[t] = make_float2(tf32r(v0 - b0), tf32r(v1 - b1));
}

// ---------------- tensor-core GEMM: C[N,128] = A[N,128] @ W[128,128], 3xTF32 ----------------
__global__ __launch_bounds__(256) void gemm_tc_kernel(const float* __restrict__ A,
                                                      const float2* __restrict__ Wb,
                                                      const float2* __restrict__ Ws,
                                                      float* __restrict__ C, int N) {
    extern __shared__ float smem[];
    float*  As = smem;                               // [128][36] = 4608 floats
    float2* Bb = (float2*)(smem + 128 * 36);         // [4][128][4] = 2048 float2
    float2* Bs = Bb + 2048;                          // 2048 float2

    int t = threadIdx.x;
    int warp = t >> 5, lane = t & 31;
    int g4 = lane >> 2, kq = lane & 3;
    int wrow = warp * 16;
    int brow0 = blockIdx.x * 128;

    float acc[16][4];
    #pragma unroll
    for (int j = 0; j < 16; j++)
        #pragma unroll
        for (int q = 0; q < 4; q++) acc[j][q] = 0.f;

    #pragma unroll
    for (int stage = 0; stage < 4; stage++) {
        __syncthreads();
        // A chunk [128][32] -> smem stride 36
        #pragma unroll
        for (int i = 0; i < 4; i++) {
            int idx = t + i * 256;
            int row = idx >> 3, c4 = idx & 7;
            float4 v = make_float4(0.f, 0.f, 0.f, 0.f);
            if (brow0 + row < N) v = ((const float4*)A)[(brow0 + row) * 32 + stage * 8 + c4];
            *(float4*)(As + row * 36 + c4 * 4) = v;
        }
        // Wb/Ws chunk: linear copy
        const float4* sb = (const float4*)(Wb + stage * 2048);
        const float4* ss = (const float4*)(Ws + stage * 2048);
        float4* db = (float4*)Bb;
        float4* ds = (float4*)Bs;
        #pragma unroll
        for (int i = 0; i < 4; i++) {
            db[t + i * 256] = sb[t + i * 256];
            ds[t + i * 256] = ss[t + i * 256];
        }
        __syncthreads();

        #pragma unroll
        for (int slab = 0; slab < 4; slab++) {
            int kb = slab * 8 + kq;
            float a0 = As[(wrow + g4) * 36 + kb];
            float a1 = As[(wrow + g4 + 8) * 36 + kb];
            float a2 = As[(wrow + g4) * 36 + kb + 4];
            float a3 = As[(wrow + g4 + 8) * 36 + kb + 4];
            float b0f = tf32r(a0), b1f = tf32r(a1), b2f = tf32r(a2), b3f = tf32r(a3);
            unsigned ab[4] = {__float_as_uint(b0f), __float_as_uint(b1f),
                              __float_as_uint(b2f), __float_as_uint(b3f)};
            unsigned al[4] = {__float_as_uint(tf32r(a0 - b0f)), __float_as_uint(tf32r(a1 - b1f)),
                              __float_as_uint(tf32r(a2 - b2f)), __float_as_uint(tf32r(a3 - b3f))};
            #pragma unroll
            for (int j = 0; j < 16; j++) {
                float2 bb = Bb[slab * 512 + (j * 8 + g4) * 4 + kq];
                float2 bs = Bs[slab * 512 + (j * 8 + g4) * 4 + kq];
                unsigned bb0 = __float_as_uint(bb.x), bb1 = __float_as_uint(bb.y);
                mma_tf32(acc[j], ab, bb0, bb1);
                mma_tf32(acc[j], al, bb0, bb1);
                mma_tf32(acc[j], ab, __float_as_uint(bs.x), __float_as_uint(bs.y));
            }
        }
    }

    int r0 = brow0 + wrow + g4;
    #pragma unroll
    for (int j = 0; j < 16; j++) {
        int col = j * 8 + kq * 2;
        if (r0 < N)     *(float2*)(C + r0 * 128 + col)       = make_float2(acc[j][0], acc[j][1]);
        if (r0 + 8 < N) *(float2*)(C + (r0 + 8) * 128 + col) = make_float2(acc[j][2], acc[j][3]);
    }
}

// ---------------- attention coefficients per (node, head) ----------------
__global__ void attn_kernel(const float* __restrict__ h, const float* __restrict__ att_src,
                            const float* __restrict__ att_dst, float* __restrict__ asrc,
                            float* __restrict__ adst, int N) {
    int i = blockIdx.x * blockDim.x + threadIdx.x;
    if (i >= N * 4) return;
    int hh = i & 3;
    const float4* hp = (const float4*)(h + (i >> 2) * 128 + hh * 32);
    const float4* sp = (const float4*)(att_src + hh * 32);
    const float4* dp = (const float4*)(att_dst + hh * 32);
    float ss = 0.f, dd = 0.f;
    #pragma unroll
    for (int j = 0; j < 8; j++) {
        float4 v = hp[j], a = sp[j], b = dp[j];
        ss += v.x * a.x + v.y * a.y + v.z * a.z + v.w * a.w;
        dd += v.x * b.x + v.y * b.y + v.z * b.z + v.w * b.w;
    }
    asrc[i] = ss;
    adst[i] = dd;
}

// ---------------- CSR build ----------------
__global__ void hist_kernel(const int* __restrict__ ei, int E, int* cnt) {
    int e = blockIdx.x * blockDim.x + threadIdx.x;
    if (e >= E) return;
    atomicAdd(cnt + ei[E + e], 1);
}

__global__ __launch_bounds__(SCAN_B) void blocksum_kernel(const int* __restrict__ cnt,
                                                          int* bsum, int N) {
    __shared__ int sh[SCAN_B];
    int i = blockIdx.x * SCAN_B + threadIdx.x;
    sh[threadIdx.x] = (i < N) ? cnt[i] : 0;
    __syncthreads();
    #pragma unroll
    for (int o = SCAN_B / 2; o; o >>= 1) {
        if (threadIdx.x < o) sh[threadIdx.x] += sh[threadIdx.x + o];
        __syncthreads();
    }
    if (threadIdx.x == 0) bsum[blockIdx.x] = sh[0];
}

__global__ __launch_bounds__(256) void bscan_kernel(const int* __restrict__ bsum,
                                                    int* boff, int NB) {
    __shared__ int sh[256];
    int t = threadIdx.x;
    sh[t] = (t < NB) ? bsum[t] : 0;
    __syncthreads();
    #pragma unroll
    for (int o = 1; o < 256; o <<= 1) {
        int v = (t >= o) ? sh[t - o] : 0;
        __syncthreads();
        sh[t] += v;
        __syncthreads();
    }
    if (t < NB) boff[t] = (t == 0) ? 0 : sh[t - 1];
}

__global__ __launch_bounds__(SCAN_B) void scanfin_kernel(const int* __restrict__ cnt,
                                                         const int* __restrict__ boff,
                                                         int* offs, int* cursor, int N, int E) {
    __shared__ int sh[SCAN_B];
    int t = threadIdx.x;
    int i = blockIdx.x * SCAN_B + t;
    int v = (i < N) ? cnt[i] : 0;
    sh[t] = v;
    __syncthreads();
    #pragma unroll
    for (int o = 1; o < SCAN_B; o <<= 1) {
        int u = (t >= o) ? sh[t - o] : 0;
        __syncthreads();
        sh[t] += u;
        __syncthreads();
    }
    if (i < N) {
        int off = boff[blockIdx.x] + sh[t] - v;
        offs[i] = off;
        cursor[i] = off;
    }
    if (i == 0) offs[N] = E;
}

__global__ void scatter_kernel(const int* __restrict__ ei, int E, int* cursor, int* csr) {
    int e = blockIdx.x * blockDim.x + threadIdx.x;
    if (e >= E) return;
    int d = ei[E + e];
    int pos = atomicAdd(cursor + d, 1);
    csr[pos] = ei[e];
}

// ---------------- GAT aggregation: warp/node, single-pass softmax, lane-parallel exp ----------------
__global__ __launch_bounds__(256) void gat_agg_kernel(const int* __restrict__ csr,
                                                      const int* __restrict__ offs,
                                                      const float* __restrict__ h,
                                                      const float* __restrict__ asrc,
                                                      const float* __restrict__ adst,
                                                      const float* __restrict__ b_gat,
                                                      const float* __restrict__ bn1w,
                                                      const float* __restrict__ bn1b,
                                                      float* __restrict__ out1,
                                                      float* __restrict__ dinv, int N) {
    int n = (blockIdx.x * 256 + threadIdx.x) >> 5;
    if (n >= N) return;
    int lane = threadIdx.x & 31;
    int hd  = lane >> 3;
    int sub = lane & 7;
    int grp = lane & 24;
    int beg = offs[n], end = offs[n + 1];

    float adn = __ldg(adst + n * 4 + hd);
    float asn = __ldg(asrc + n * 4 + hd);
    float wself = __expf(lrelu(asn + adn));

    float4 hv = *(const float4*)(h + n * 128 + lane * 4);
    float4 acc = make_float4(hv.x * wself, hv.y * wself, hv.z * wself, hv.w * wself);

    float wpart = 0.f;
    for (int c0 = beg; c0 < end; c0 += 8) {
        int e = c0 + sub;
        float w = 0.f; int s = 0;
        if (e < end) {
            s = __ldg(csr + e);
            w = __expf(lrelu(__ldg(asrc + s * 4 + hd) + adn));
        }
        wpart += w;
        int cnt = min(8, end - c0);
        for (int i = 0; i < cnt; i++) {
            int   si = __shfl_sync(0xffffffffu, s, i);
            float a  = __shfl_sync(0xffffffffu, w, grp + i);
            float4 hs = *(const float4*)(h + si * 128 + lane * 4);
            acc.x += hs.x * a; acc.y += hs.y * a; acc.z += hs.z * a; acc.w += hs.w * a;
        }
    }

    #pragma unroll
    for (int o = 1; o < 8; o <<= 1) wpart += __shfl_xor_sync(0xffffffffu, wpart, o);
    float inv = 1.f / (wpart + wself + 1e-16f);

    int c = lane * 4;
    float4 bb = *(const float4*)(b_gat + c);
    float4 w1 = *(const float4*)(bn1w + c);
    float4 b1 = *(const float4*)(bn1b + c);
    float4 v;
    v.x = elu_f(acc.x * inv + bb.x) * w1.x + b1.x;
    v.y = elu_f(acc.y * inv + bb.y) * w1.y + b1.y;
    v.z = elu_f(acc.z * inv + bb.z) * w1.z + b1.z;
    v.w = elu_f(acc.w * inv + bb.w) * w1.w + b1.w;
    *(float4*)(out1 + n * 128 + c) = v;

    if (lane == 0) dinv[n] = rsqrtf((float)(end - beg + 1));
}

// ---------------- GCN aggregation + gate ----------------
__global__ __launch_bounds__(256) void gcn_agg_kernel(const int* __restrict__ csr,
                                                      const int* __restrict__ offs,
                                                      const float* __restrict__ h2,
                                                      const float* __restrict__ dinv,
                                                      const float* __restrict__ b_gcn,
                                                      const float* __restrict__ bn2w,
                                                      const float* __restrict__ bn2b,
                                                      const float* __restrict__ W_gate,
                                                      const float* __restrict__ b_gate,
                                                      float* __restrict__ out2,
                                                      float* __restrict__ gate, int N) {
    int n = (blockIdx.x * 256 + threadIdx.x) >> 5;
    if (n >= N) return;
    int lane = threadIdx.x & 31;
    int sub = lane & 7;
    int beg = offs[n], end = offs[n + 1];
    float dn = __ldg(dinv + n);

    float4 hv = *(const float4*)(h2 + n * 128 + lane * 4);
    float fs = dn * dn;
    float4 acc = make_float4(hv.x * fs, hv.y * fs, hv.z * fs, hv.w * fs);

    for (int c0 = beg; c0 < end; c0 += 8) {
        int e = c0 + sub;
        float f = 0.f; int s = 0;
        if (e < end) {
            s = __ldg(csr + e);
            f = __ldg(dinv + s) * dn;
        }
        int cnt = min(8, end - c0);
        for (int i = 0; i < cnt; i++) {
            int   si = __shfl_sync(0xffffffffu, s, i);
            float a  = __shfl_sync(0xffffffffu, f, i);
            float4 hs = *(const float4*)(h2 + si * 128 + lane * 4);
            acc.x += hs.x * a; acc.y += hs.y * a; acc.z += hs.z * a; acc.w += hs.w * a;
        }
    }

    int c = lane * 4;
    float4 bb = *(const float4*)(b_gcn + c);
    float4 w2 = *(const float4*)(bn2w + c);
    float4 b2 = *(const float4*)(bn2b + c);
    float4 v;
    v.x = elu_f(acc.x + bb.x) * w2.x + b2.x;
    v.y = elu_f(acc.y + bb.y) * w2.y + b2.y;
    v.z = elu_f(acc.z + bb.z) * w2.z + b2.z;
    v.w = elu_f(acc.w + bb.w) * w2.w + b2.w;
    *(float4*)(out2 + n * 128 + c) = v;

    float4 wg = *(const float4*)(W_gate + c);
    float p = v.x * wg.x + v.y * wg.y + v.z * wg.z + v.w * wg.w;
    #pragma unroll
    for (int o = 16; o; o >>= 1) p += __shfl_xor_sync(0xffffffffu, p, o);
    if (lane == 0) gate[n] = p + b_gate[0];
}

// ---------------- pooling + FC ----------------
__global__ __launch_bounds__(256) void pool_kernel(const float* __restrict__ out2,
                                                   const float* __restrict__ gate,
                                                   const int* __restrict__ gs,
                                                   const int* __restrict__ ge,
                                                   const float* __restrict__ W_fc,
                                                   const float* __restrict__ b_fc,
                                                   float* __restrict__ out) {
    int g = blockIdx.x;
    int start = gs[g], end = ge[g];
    int tid = threadIdx.x;
    __shared__ float red[256];
    __shared__ float wsh[256];

    float mx = -3.4e38f;
    for (int n = start + tid; n < end; n += 256) mx = fmaxf(mx, gate[n]);
    red[tid] = mx;
    __syncthreads();
    #pragma unroll
    for (int o = 128; o; o >>= 1) {
        if (tid < o) red[tid] = fmaxf(red[tid], red[tid + o]);
        __syncthreads();
    }
    float gmax = red[0];
    __syncthreads();

    int c = tid & 127, half = tid >> 7;
    float acc = 0.f, wloc = 0.f;
    for (int t0 = start; t0 < end; t0 += 256) {
        int tc = min(256, end - t0);
        if (tid < tc) {
            float wv = __expf(gate[t0 + tid] - gmax);
            wsh[tid] = wv;
            wloc += wv;
        }
        __syncthreads();
        for (int j = half; j < tc; j += 2)
            acc += wsh[j] * out2[(t0 + j) * 128 + c];
        __syncthreads();
    }

    red[tid] = wloc;
    __syncthreads();
    #pragma unroll
    for (int o = 128; o; o >>= 1) {
        if (tid < o) red[tid] += red[tid + o];
        __syncthreads();
    }
    float wsum = red[0];
    __syncthreads();

    red[tid] = acc;
    __syncthreads();
    float val = 0.f;
    if (tid < 128) val = (red[tid] + red[tid + 128]) / (wsum + 1e-16f) * W_fc[tid];
    __syncthreads();
    red[tid] = (tid < 128) ? val : 0.f;
    __syncthreads();
    #pragma unroll
    for (int o = 128; o; o >>= 1) {
        if (tid < o) red[tid] += red[tid + o];
        __syncthreads();
    }
    if (tid == 0) out[g] = red[0] + b_fc[0];
}

// ---------------- launch ----------------
extern "C" void kernel_launch(void* const* d_in, const int* in_sizes, int n_in,
                              void* d_out, int out_size) {
    const float* x       = (const float*)d_in[0];
    const int*   ei      = (const int*)d_in[1];
    const int*   batch   = (const int*)d_in[2];
    const float* W_gat   = (const float*)d_in[3];
    const float* att_src = (const float*)d_in[4];
    const float* att_dst = (const float*)d_in[5];
    const float* b_gat   = (const float*)d_in[6];
    const float* bn1w    = (const float*)d_in[7];
    const float* bn1b    = (const float*)d_in[8];
    const float* W_gcn   = (const float*)d_in[9];
    const float* b_gcn   = (const float*)d_in[10];
    const float* bn2w    = (const float*)d_in[11];
    const float* bn2b    = (const float*)d_in[12];
    const float* W_gate  = (const float*)d_in[13];
    const float* b_gate  = (const float*)d_in[14];
    const float* W_fc    = (const float*)d_in[15];
    const float* b_fc    = (const float*)d_in[16];
    float* out = (float*)d_out;

    int N = in_sizes[0] / 128;
    int E = in_sizes[1] / 2;
    int NB = (N + SCAN_B - 1) / SCAN_B;
    const int GEMM_SMEM = 128 * 36 * 4 + 2 * 2048 * 8;   // 51200 B

    cudaFuncSetAttribute(gemm_tc_kernel, cudaFuncAttributeMaxDynamicSharedMemorySize,
                         GEMM_SMEM);

    float *p_h, *p_h2, *p_asrc, *p_adst, *p_out1, *p_out2, *p_gate, *p_dinv;
    float2 *p_wb1, *p_ws1, *p_wb2, *p_ws2;
    int *p_cnt, *p_offs, *p_cursor, *p_csr, *p_bsum, *p_boff, *p_gs, *p_ge;
    cudaGetSymbolAddress((void**)&p_h,     g_h);
    cudaGetSymbolAddress((void**)&p_h2,    g_h2);
    cudaGetSymbolAddress((void**)&p_asrc,  g_asrc);
    cudaGetSymbolAddress((void**)&p_adst,  g_adst);
    cudaGetSymbolAddress((void**)&p_out1,  g_out1);
    cudaGetSymbolAddress((void**)&p_out2,  g_out2);
    cudaGetSymbolAddress((void**)&p_gate,  g_gate);
    cudaGetSymbolAddress((void**)&p_dinv,  g_dinv);
    cudaGetSymbolAddress((void**)&p_cnt,   g_cnt);
    cudaGetSymbolAddress((void**)&p_offs,  g_offs);
    cudaGetSymbolAddress((void**)&p_cursor,g_cursor);
    cudaGetSymbolAddress((void**)&p_csr,   g_csr);
    cudaGetSymbolAddress((void**)&p_bsum,  g_bsum);
    cudaGetSymbolAddress((void**)&p_boff,  g_boff);
    cudaGetSymbolAddress((void**)&p_gs,    g_gstart);
    cudaGetSymbolAddress((void**)&p_ge,    g_gend);
    cudaGetSymbolAddress((void**)&p_wb1,   g_wb1);
    cudaGetSymbolAddress((void**)&p_ws1,   g_ws1);
    cudaGetSymbolAddress((void**)&p_wb2,   g_wb2);
    cudaGetSymbolAddress((void**)&p_ws2,   g_ws2);

    int gblk = (N + 127) / 128;

    init_kernel<<<(N + 255) / 256, 256>>>(p_cnt, p_gs, p_ge, N);                    // 0
    bounds_kernel<<<(N + 255) / 256, 256>>>(batch, p_gs, p_ge, N);                  // 1
    wpack_kernel<<<32, 256>>>(W_gat, p_wb1, p_ws1);                                 // 2
    gemm_tc_kernel<<<gblk, 256, GEMM_SMEM>>>(x, p_wb1, p_ws1, p_h, N);              // 3 (ncu)
    wpack_kernel<<<32, 256>>>(W_gcn, p_wb2, p_ws2);                                 // 4
    hist_kernel<<<(E + 255) / 256, 256>>>(ei, E, p_cnt);                            // 5
    blocksum_kernel<<<NB, SCAN_B>>>(p_cnt, p_bsum, N);                              // 6
    bscan_kernel<<<1, 256>>>(p_bsum, p_boff, NB);                                   // 7
    scanfin_kernel<<<NB, SCAN_B>>>(p_cnt, p_boff, p_offs, p_cursor, N, E);          // 8
    scatter_kernel<<<(E + 255) / 256, 256>>>(ei, E, p_cursor, p_csr);               // 9
    attn_kernel<<<(N * 4 + 255) / 256, 256>>>(p_h, att_src, att_dst, p_asrc, p_adst, N); // 10
    gat_agg_kernel<<<(N * 32 + 255) / 256, 256>>>(p_csr, p_offs, p_h, p_asrc, p_adst,
                                                  b_gat, bn1w, bn1b, p_out1, p_dinv, N); // 11
    gemm_tc_kernel<<<gblk, 256, GEMM_SMEM>>>(p_out1, p_wb2, p_ws2, p_h2, N);        // 12
    gcn_agg_kernel<<<(N * 32 + 255) / 256, 256>>>(p_csr, p_offs, p_h2, p_dinv,
                                                  b_gcn, bn2w, bn2b, W_gate, b_gate,
                                                  p_out2, p_gate, N);               // 13
    pool_kernel<<<64, 256>>>(p_out2, p_gate, p_gs, p_ge, W_fc, b_fc, out);          // 14
}

// round 8
// speedup vs baseline: 2.0179x; 1.1489x over previous
#include <cuda_runtime.h>
#include <cuda_bf16.h>
#include <math.h>

#define NMAX 50048
#define EMAX 800000
#define SCAN_B 256

// ---------------- scratch (device globals) ----------------
__device__ float g_h[NMAX * 128];      // x @ W_gat
__device__ float g_h2[NMAX * 128];     // out1 @ W_gcn
__device__ float g_asrc[NMAX * 4];
__device__ float g_adst[NMAX * 4];
__device__ float g_out1[NMAX * 128];
__device__ float g_out2[NMAX * 128];
__device__ float g_gate[NMAX];
__device__ float g_dinv[NMAX];
__device__ int   g_cnt[NMAX];
__device__ int   g_offs[NMAX + 1];
__device__ int   g_cursor[NMAX];
__device__ int   g_csr[EMAX];
__device__ int   g_bsum[(NMAX + SCAN_B - 1) / SCAN_B];
__device__ int   g_boff[(NMAX + SCAN_B - 1) / SCAN_B];
__device__ int   g_gstart[64];
__device__ int   g_gend[64];
// packed bf16 hi/lo weights, fragment order: [slab8][col128][kq4] uint2
// uint2.x = bf16pair(W[k0][col], W[k0+1][col]), uint2.y = pair(W[k0+8], W[k0+9]), k0=slab*16+2kq
__device__ uint2 g_wh1[4096];
__device__ uint2 g_wl1[4096];
__device__ uint2 g_wh2[4096];
__device__ uint2 g_wl2[4096];

// ---------------- helpers ----------------
__device__ __forceinline__ float lrelu(float v) { return v > 0.f ? v : 0.2f * v; }
__device__ __forceinline__ float elu_f(float v) { return v > 0.f ? v : (__expf(v) - 1.f); }

__device__ __forceinline__ void split_bf(float x, float y, unsigned& hi, unsigned& lo) {
    __nv_bfloat162 h = __floats2bfloat162_rn(x, y);
    float rx = x - __bfloat162float(h.x);
    float ry = y - __bfloat162float(h.y);
    __nv_bfloat162 l = __floats2bfloat162_rn(rx, ry);
    hi = *(unsigned*)&h;
    lo = *(unsigned*)&l;
}

__device__ __forceinline__ void mma_bf16(float* d, const unsigned* a, unsigned b0, unsigned b1) {
    asm("mma.sync.aligned.m16n8k16.row.col.f32.bf16.bf16.f32 "
        "{%0,%1,%2,%3},{%4,%5,%6,%7},{%8,%9},{%0,%1,%2,%3};"
        : "+f"(d[0]), "+f"(d[1]), "+f"(d[2]), "+f"(d[3])
        : "r"(a[0]), "r"(a[1]), "r"(a[2]), "r"(a[3]), "r"(b0), "r"(b1));
}

// ---------------- init (+ graph bounds fused) ----------------
__global__ void init_kernel(int* cnt, int* gs, int* ge, const int* __restrict__ batch, int N) {
    int i = blockIdx.x * blockDim.x + threadIdx.x;
    if (i < N) {
        cnt[i] = 0;
        int b = batch[i];
        if (i == 0 || batch[i - 1] != b) gs[b] = i;
        if (i == N - 1 || batch[i + 1] != b) ge[b] = i + 1;
    }
}

// ---------------- CSR: histogram ----------------
__global__ void hist_kernel(const int* __restrict__ ei, int E, int* cnt) {
    int e = blockIdx.x * blockDim.x + threadIdx.x;
    if (e >= E) return;
    atomicAdd(cnt + ei[E + e], 1);
}

// ---------------- pack BOTH weight matrices into bf16 hi/lo fragment order ----------------
__global__ void wpack_kernel(const float* __restrict__ W1, const float* __restrict__ W2,
                             uint2* Wh1, uint2* Wl1, uint2* Wh2, uint2* Wl2) {
    int t = blockIdx.x * blockDim.x + threadIdx.x;
    if (t >= 8192) return;
    const float* W = (t < 4096) ? W1 : W2;
    uint2* Wh = (t < 4096) ? Wh1 : Wh2;
    uint2* Wl = (t < 4096) ? Wl1 : Wl2;
    int i = t & 4095;
    int kq   = i & 3;
    int col  = (i >> 2) & 127;
    int slab = i >> 9;
    int k0 = slab * 16 + 2 * kq;
    uint2 h, l;
    split_bf(W[k0 * 128 + col],       W[(k0 + 1) * 128 + col], h.x, l.x);
    split_bf(W[(k0 + 8) * 128 + col], W[(k0 + 9) * 128 + col], h.y, l.y);
    Wh[i] = h;
    Wl[i] = l;
}

// ---------------- tensor-core GEMM: C[N,128] = A[N,128] @ W[128,128], 3xBF16 ----------------
// block: 128 rows, 8 warps x 16 rows; warp covers all 128 cols.
template <bool ATTN>
__global__ __launch_bounds__(256) void gemm_tc_kernel(const float* __restrict__ A,
                                                      const uint2* __restrict__ Wh,
                                                      const uint2* __restrict__ Wl,
                                                      float* __restrict__ C,
                                                      const float* __restrict__ att_src,
                                                      const float* __restrict__ att_dst,
                                                      float* __restrict__ asrc,
                                                      float* __restrict__ adst, int N) {
    __shared__ float As[128 * 36];       // 18432 B (stage of 32 k-cols, stride 36)
    __shared__ uint2 Bh[1024];           // 8192 B (2 slabs)
    __shared__ uint2 Bl[1024];           // 8192 B

    int t = threadIdx.x;
    int warp = t >> 5, lane = t & 31;
    int g4 = lane >> 2, kq = lane & 3;
    int wrow = warp * 16;
    int brow0 = blockIdx.x * 128;

    float acc[16][4];
    #pragma unroll
    for (int j = 0; j < 16; j++)
        #pragma unroll
        for (int q = 0; q < 4; q++) acc[j][q] = 0.f;

    #pragma unroll
    for (int stage = 0; stage < 4; stage++) {
        __syncthreads();
        // A chunk [128][32] -> smem stride 36
        #pragma unroll
        for (int i = 0; i < 4; i++) {
            int idx = t + i * 256;
            int row = idx >> 3, c4 = idx & 7;
            float4 v = make_float4(0.f, 0.f, 0.f, 0.f);
            if (brow0 + row < N) v = ((const float4*)A)[(brow0 + row) * 32 + stage * 8 + c4];
            *(float4*)(As + row * 36 + c4 * 4) = v;
        }
        // W chunk: 1024 uint2 each (linear)
        {
            const float4* sh = (const float4*)(Wh + stage * 1024);
            const float4* sl = (const float4*)(Wl + stage * 1024);
            float4* dh = (float4*)Bh;
            float4* dl = (float4*)Bl;
            #pragma unroll
            for (int i = 0; i < 2; i++) {
                dh[t + i * 256] = sh[t + i * 256];
                dl[t + i * 256] = sl[t + i * 256];
            }
        }
        __syncthreads();

        #pragma unroll
        for (int sl = 0; sl < 2; sl++) {
            int kb = sl * 16 + 2 * kq;
            float2 A0 = *(const float2*)(As + (wrow + g4) * 36 + kb);
            float2 A1 = *(const float2*)(As + (wrow + g4) * 36 + kb + 8);
            float2 A2 = *(const float2*)(As + (wrow + g4 + 8) * 36 + kb);
            float2 A3 = *(const float2*)(As + (wrow + g4 + 8) * 36 + kb + 8);
            unsigned ah[4], al[4];
            split_bf(A0.x, A0.y, ah[0], al[0]);
            split_bf(A2.x, A2.y, ah[1], al[1]);
            split_bf(A1.x, A1.y, ah[2], al[2]);
            split_bf(A3.x, A3.y, ah[3], al[3]);
            #pragma unroll
            for (int j = 0; j < 16; j++) {
                uint2 bh = Bh[sl * 512 + (j * 8 + g4) * 4 + kq];
                uint2 bl = Bl[sl * 512 + (j * 8 + g4) * 4 + kq];
                mma_bf16(acc[j], ah, bh.x, bh.y);
                mma_bf16(acc[j], al, bh.x, bh.y);
                mma_bf16(acc[j], ah, bl.x, bl.y);
            }
        }
    }

    int r0 = brow0 + wrow + g4;
    #pragma unroll
    for (int j = 0; j < 16; j++) {
        int col = j * 8 + kq * 2;
        if (r0 < N)     *(float2*)(C + r0 * 128 + col)       = make_float2(acc[j][0], acc[j][1]);
        if (r0 + 8 < N) *(float2*)(C + (r0 + 8) * 128 + col) = make_float2(acc[j][2], acc[j][3]);
    }

    if (ATTN) {
        #pragma unroll
        for (int hh = 0; hh < 4; hh++) {
            float psl = 0.f, psh = 0.f, pdl = 0.f, pdh = 0.f;
            #pragma unroll
            for (int jj = 0; jj < 4; jj++) {
                int j = hh * 4 + jj;
                float2 av = *(const float2*)(att_src + j * 8 + 2 * kq);
                float2 dv = *(const float2*)(att_dst + j * 8 + 2 * kq);
                psl += acc[j][0] * av.x + acc[j][1] * av.y;
                psh += acc[j][2] * av.x + acc[j][3] * av.y;
                pdl += acc[j][0] * dv.x + acc[j][1] * dv.y;
                pdh += acc[j][2] * dv.x + acc[j][3] * dv.y;
            }
            psl += __shfl_xor_sync(0xffffffffu, psl, 1);
            psl += __shfl_xor_sync(0xffffffffu, psl, 2);
            psh += __shfl_xor_sync(0xffffffffu, psh, 1);
            psh += __shfl_xor_sync(0xffffffffu, psh, 2);
            pdl += __shfl_xor_sync(0xffffffffu, pdl, 1);
            pdl += __shfl_xor_sync(0xffffffffu, pdl, 2);
            pdh += __shfl_xor_sync(0xffffffffu, pdh, 1);
            pdh += __shfl_xor_sync(0xffffffffu, pdh, 2);
            if (kq == 0) {
                if (r0 < N)     { asrc[r0 * 4 + hh] = psl;       adst[r0 * 4 + hh] = pdl; }
                if (r0 + 8 < N) { asrc[(r0 + 8) * 4 + hh] = psh; adst[(r0 + 8) * 4 + hh] = pdh; }
            }
        }
    }
}

// ---------------- CSR scan ----------------
__global__ __launch_bounds__(SCAN_B) void blocksum_kernel(const int* __restrict__ cnt,
                                                          int* bsum, int N) {
    __shared__ int sh[SCAN_B];
    int i = blockIdx.x * SCAN_B + threadIdx.x;
    sh[threadIdx.x] = (i < N) ? cnt[i] : 0;
    __syncthreads();
    #pragma unroll
    for (int o = SCAN_B / 2; o; o >>= 1) {
        if (threadIdx.x < o) sh[threadIdx.x] += sh[threadIdx.x + o];
        __syncthreads();
    }
    if (threadIdx.x == 0) bsum[blockIdx.x] = sh[0];
}

__global__ __launch_bounds__(256) void bscan_kernel(const int* __restrict__ bsum,
                                                    int* boff, int NB) {
    __shared__ int sh[256];
    int t = threadIdx.x;
    sh[t] = (t < NB) ? bsum[t] : 0;
    __syncthreads();
    #pragma unroll
    for (int o = 1; o < 256; o <<= 1) {
        int v = (t >= o) ? sh[t - o] : 0;
        __syncthreads();
        sh[t] += v;
        __syncthreads();
    }
    if (t < NB) boff[t] = (t == 0) ? 0 : sh[t - 1];
}

__global__ __launch_bounds__(SCAN_B) void scanfin_kernel(const int* __restrict__ cnt,
                                                         const int* __restrict__ boff,
                                                         int* offs, int* cursor, int N, int E) {
    __shared__ int sh[SCAN_B];
    int t = threadIdx.x;
    int i = blockIdx.x * SCAN_B + t;
    int v = (i < N) ? cnt[i] : 0;
    sh[t] = v;
    __syncthreads();
    #pragma unroll
    for (int o = 1; o < SCAN_B; o <<= 1) {
        int u = (t >= o) ? sh[t - o] : 0;
        __syncthreads();
        sh[t] += u;
        __syncthreads();
    }
    if (i < N) {
        int off = boff[blockIdx.x] + sh[t] - v;
        offs[i] = off;
        cursor[i] = off;
    }
    if (i == 0) offs[N] = E;
}

__global__ void scatter_kernel(const int* __restrict__ ei, int E, int* cursor, int* csr) {
    int e = blockIdx.x * blockDim.x + threadIdx.x;
    if (e >= E) return;
    int d = ei[E + e];
    int pos = atomicAdd(cursor + d, 1);
    csr[pos] = ei[e];
}

// ---------------- GAT aggregation: warp/node, single-pass softmax, lane-parallel exp ----------------
__global__ __launch_bounds__(256) void gat_agg_kernel(const int* __restrict__ csr,
                                                      const int* __restrict__ offs,
                                                      const float* __restrict__ h,
                                                      const float* __restrict__ asrc,
                                                      const float* __restrict__ adst,
                                                      const float* __restrict__ b_gat,
                                                      const float* __restrict__ bn1w,
                                                      const float* __restrict__ bn1b,
                                                      float* __restrict__ out1,
                                                      float* __restrict__ dinv, int N) {
    int n = (blockIdx.x * 256 + threadIdx.x) >> 5;
    if (n >= N) return;
    int lane = threadIdx.x & 31;
    int hd  = lane >> 3;
    int sub = lane & 7;
    int grp = lane & 24;
    int beg = offs[n], end = offs[n + 1];

    float adn = __ldg(adst + n * 4 + hd);
    float asn = __ldg(asrc + n * 4 + hd);
    float wself = __expf(lrelu(asn + adn));

    float4 hv = *(const float4*)(h + n * 128 + lane * 4);
    float4 acc = make_float4(hv.x * wself, hv.y * wself, hv.z * wself, hv.w * wself);

    float wpart = 0.f;
    for (int c0 = beg; c0 < end; c0 += 8) {
        int e = c0 + sub;
        float w = 0.f; int s = 0;
        if (e < end) {
            s = __ldg(csr + e);
            w = __expf(lrelu(__ldg(asrc + s * 4 + hd) + adn));
        }
        wpart += w;
        int cnt = min(8, end - c0);
        for (int i = 0; i < cnt; i++) {
            int   si = __shfl_sync(0xffffffffu, s, i);
            float a  = __shfl_sync(0xffffffffu, w, grp + i);
            float4 hs = *(const float4*)(h + si * 128 + lane * 4);
            acc.x += hs.x * a; acc.y += hs.y * a; acc.z += hs.z * a; acc.w += hs.w * a;
        }
    }

    #pragma unroll
    for (int o = 1; o < 8; o <<= 1) wpart += __shfl_xor_sync(0xffffffffu, wpart, o);
    float inv = 1.f / (wpart + wself + 1e-16f);

    int c = lane * 4;
    float4 bb = *(const float4*)(b_gat + c);
    float4 w1 = *(const float4*)(bn1w + c);
    float4 b1 = *(const float4*)(bn1b + c);
    float4 v;
    v.x = elu_f(acc.x * inv + bb.x) * w1.x + b1.x;
    v.y = elu_f(acc.y * inv + bb.y) * w1.y + b1.y;
    v.z = elu_f(acc.z * inv + bb.z) * w1.z + b1.z;
    v.w = elu_f(acc.w * inv + bb.w) * w1.w + b1.w;
    *(float4*)(out1 + n * 128 + c) = v;

    if (lane == 0) dinv[n] = rsqrtf((float)(end - beg + 1));
}

// ---------------- GCN aggregation + gate ----------------
__global__ __launch_bounds__(256) void gcn_agg_kernel(const int* __restrict__ csr,
                                                      const int* __restrict__ offs,
                                                      const float* __restrict__ h2,
                                                      const float* __restrict__ dinv,
                                                      const float* __restrict__ b_gcn,
                                                      const float* __restrict__ bn2w,
                                                      const float* __restrict__ bn2b,
                                                      const float* __restrict__ W_gate,
                                                      const float* __restrict__ b_gate,
                                                      float* __restrict__ out2,
                                                      float* __restrict__ gate, int N) {
    int n = (blockIdx.x * 256 + threadIdx.x) >> 5;
    if (n >= N) return;
    int lane = threadIdx.x & 31;
    int sub = lane & 7;
    int beg = offs[n], end = offs[n + 1];
    float dn = __ldg(dinv + n);

    float4 hv = *(const float4*)(h2 + n * 128 + lane * 4);
    float fs = dn * dn;
    float4 acc = make_float4(hv.x * fs, hv.y * fs, hv.z * fs, hv.w * fs);

    for (int c0 = beg; c0 < end; c0 += 8) {
        int e = c0 + sub;
        float f = 0.f; int s = 0;
        if (e < end) {
            s = __ldg(csr + e);
            f = __ldg(dinv + s) * dn;
        }
        int cnt = min(8, end - c0);
        for (int i = 0; i < cnt; i++) {
            int   si = __shfl_sync(0xffffffffu, s, i);
            float a  = __shfl_sync(0xffffffffu, f, i);
            float4 hs = *(const float4*)(h2 + si * 128 + lane * 4);
            acc.x += hs.x * a; acc.y += hs.y * a; acc.z += hs.z * a; acc.w += hs.w * a;
        }
    }

    int c = lane * 4;
    float4 bb = *(const float4*)(b_gcn + c);
    float4 w2 = *(const float4*)(bn2w + c);
    float4 b2 = *(const float4*)(bn2b + c);
    float4 v;
    v.x = elu_f(acc.x + bb.x) * w2.x + b2.x;
    v.y = elu_f(acc.y + bb.y) * w2.y + b2.y;
    v.z = elu_f(acc.z + bb.z) * w2.z + b2.z;
    v.w = elu_f(acc.w + bb.w) * w2.w + b2.w;
    *(float4*)(out2 + n * 128 + c) = v;

    float4 wg = *(const float4*)(W_gate + c);
    float p = v.x * wg.x + v.y * wg.y + v.z * wg.z + v.w * wg.w;
    #pragma unroll
    for (int o = 16; o; o >>= 1) p += __shfl_xor_sync(0xffffffffu, p, o);
    if (lane == 0) gate[n] = p + b_gate[0];
}

// ---------------- pooling + FC ----------------
__global__ __launch_bounds__(256) void pool_kernel(const float* __restrict__ out2,
                                                   const float* __restrict__ gate,
                                                   const int* __restrict__ gs,
                                                   const int* __restrict__ ge,
                                                   const float* __restrict__ W_fc,
                                                   const float* __restrict__ b_fc,
                                                   float* __restrict__ out) {
    int g = blockIdx.x;
    int start = gs[g], end = ge[g];
    int tid = threadIdx.x;
    __shared__ float red[256];
    __shared__ float wsh[256];

    float mx = -3.4e38f;
    for (int n = start + tid; n < end; n += 256) mx = fmaxf(mx, gate[n]);
    red[tid] = mx;
    __syncthreads();
    #pragma unroll
    for (int o = 128; o; o >>= 1) {
        if (tid < o) red[tid] = fmaxf(red[tid], red[tid + o]);
        __syncthreads();
    }
    float gmax = red[0];
    __syncthreads();

    int c = tid & 127, half = tid >> 7;
    float acc = 0.f, wloc = 0.f;
    for (int t0 = start; t0 < end; t0 += 256) {
        int tc = min(256, end - t0);
        if (tid < tc) {
            float wv = __expf(gate[t0 + tid] - gmax);
            wsh[tid] = wv;
            wloc += wv;
        }
        __syncthreads();
        for (int j = half; j < tc; j += 2)
            acc += wsh[j] * out2[(t0 + j) * 128 + c];
        __syncthreads();
    }

    red[tid] = wloc;
    __syncthreads();
    #pragma unroll
    for (int o = 128; o; o >>= 1) {
        if (tid < o) red[tid] += red[tid + o];
        __syncthreads();
    }
    float wsum = red[0];
    __syncthreads();

    red[tid] = acc;
    __syncthreads();
    float val = 0.f;
    if (tid < 128) val = (red[tid] + red[tid + 128]) / (wsum + 1e-16f) * W_fc[tid];
    __syncthreads();
    red[tid] = (tid < 128) ? val : 0.f;
    __syncthreads();
    #pragma unroll
    for (int o = 128; o; o >>= 1) {
        if (tid < o) red[tid] += red[tid + o];
        __syncthreads();
    }
    if (tid == 0) out[g] = red[0] + b_fc[0];
}

// ---------------- launch ----------------
extern "C" void kernel_launch(void* const* d_in, const int* in_sizes, int n_in,
                              void* d_out, int out_size) {
    const float* x       = (const float*)d_in[0];
    const int*   ei      = (const int*)d_in[1];
    const int*   batch   = (const int*)d_in[2];
    const float* W_gat   = (const float*)d_in[3];
    const float* att_src = (const float*)d_in[4];
    const float* att_dst = (const float*)d_in[5];
    const float* b_gat   = (const float*)d_in[6];
    const float* bn1w    = (const float*)d_in[7];
    const float* bn1b    = (const float*)d_in[8];
    const float* W_gcn   = (const float*)d_in[9];
    const float* b_gcn   = (const float*)d_in[10];
    const float* bn2w    = (const float*)d_in[11];
    const float* bn2b    = (const float*)d_in[12];
    const float* W_gate  = (const float*)d_in[13];
    const float* b_gate  = (const float*)d_in[14];
    const float* W_fc    = (const float*)d_in[15];
    const float* b_fc    = (const float*)d_in[16];
    float* out = (float*)d_out;

    int N = in_sizes[0] / 128;
    int E = in_sizes[1] / 2;
    int NB = (N + SCAN_B - 1) / SCAN_B;

    float *p_h, *p_h2, *p_asrc, *p_adst, *p_out1, *p_out2, *p_gate, *p_dinv;
    uint2 *p_wh1, *p_wl1, *p_wh2, *p_wl2;
    int *p_cnt, *p_offs, *p_cursor, *p_csr, *p_bsum, *p_boff, *p_gs, *p_ge;
    cudaGetSymbolAddress((void**)&p_h,     g_h);
    cudaGetSymbolAddress((void**)&p_h2,    g_h2);
    cudaGetSymbolAddress((void**)&p_asrc,  g_asrc);
    cudaGetSymbolAddress((void**)&p_adst,  g_adst);
    cudaGetSymbolAddress((void**)&p_out1,  g_out1);
    cudaGetSymbolAddress((void**)&p_out2,  g_out2);
    cudaGetSymbolAddress((void**)&p_gate,  g_gate);
    cudaGetSymbolAddress((void**)&p_dinv,  g_dinv);
    cudaGetSymbolAddress((void**)&p_cnt,   g_cnt);
    cudaGetSymbolAddress((void**)&p_offs,  g_offs);
    cudaGetSymbolAddress((void**)&p_cursor,g_cursor);
    cudaGetSymbolAddress((void**)&p_csr,   g_csr);
    cudaGetSymbolAddress((void**)&p_bsum,  g_bsum);
    cudaGetSymbolAddress((void**)&p_boff,  g_boff);
    cudaGetSymbolAddress((void**)&p_gs,    g_gstart);
    cudaGetSymbolAddress((void**)&p_ge,    g_gend);
    cudaGetSymbolAddress((void**)&p_wh1,   g_wh1);
    cudaGetSymbolAddress((void**)&p_wl1,   g_wl1);
    cudaGetSymbolAddress((void**)&p_wh2,   g_wh2);
    cudaGetSymbolAddress((void**)&p_wl2,   g_wl2);

    int gblk = (N + 127) / 128;

    init_kernel<<<(N + 255) / 256, 256>>>(p_cnt, p_gs, p_ge, batch, N);             // 0
    hist_kernel<<<(E + 255) / 256, 256>>>(ei, E, p_cnt);                            // 1
    wpack_kernel<<<32, 256>>>(W_gat, W_gcn, p_wh1, p_wl1, p_wh2, p_wl2);            // 2
    gemm_tc_kernel<true><<<gblk, 256>>>(x, p_wh1, p_wl1, p_h, att_src, att_dst,
                                        p_asrc, p_adst, N);                         // 3 (ncu)
    blocksum_kernel<<<NB, SCAN_B>>>(p_cnt, p_bsum, N);                              // 4
    bscan_kernel<<<1, 256>>>(p_bsum, p_boff, NB);                                   // 5
    scanfin_kernel<<<NB, SCAN_B>>>(p_cnt, p_boff, p_offs, p_cursor, N, E);          // 6
    scatter_kernel<<<(E + 255) / 256, 256>>>(ei, E, p_cursor, p_csr);               // 7
    gat_agg_kernel<<<(N * 32 + 255) / 256, 256>>>(p_csr, p_offs, p_h, p_asrc, p_adst,
                                                  b_gat, bn1w, bn1b, p_out1, p_dinv, N); // 8
    gemm_tc_kernel<false><<<gblk, 256>>>(p_out1, p_wh2, p_wl2, p_h2, nullptr, nullptr,
                                         nullptr, nullptr, N);                      // 9
    gcn_agg_kernel<<<(N * 32 + 255) / 256, 256>>>(p_csr, p_offs, p_h2, p_dinv,
                                                  b_gcn, bn2w, bn2b, W_gate, b_gate,
                                                  p_out2, p_gate, N);               // 10
    pool_kernel<<<64, 256>>>(p_out2, p_gate, p_gs, p_ge, W_fc, b_fc, out);          // 11
}

// round 9
// speedup vs baseline: 2.1434x; 1.0622x over previous
#include <cuda_runtime.h>
#include <cuda_bf16.h>
#include <math.h>

#define NMAX 50048
#define EMAX 800000
#define SCAN_B 256

// ---------------- scratch (device globals) ----------------
__device__ float g_h[NMAX * 128];      // x @ W_gat
__device__ float g_h2[NMAX * 128];     // out1 @ W_gcn
__device__ float g_asrc[NMAX * 4];
__device__ float g_adst[NMAX * 4];
__device__ float g_out1[NMAX * 128];
__device__ float g_out2[NMAX * 128];
__device__ float g_gate[NMAX];
__device__ float g_dinv[NMAX];
__device__ int   g_cnt[NMAX];
__device__ int   g_offs[NMAX + 1];
__device__ int   g_cursor[NMAX];
__device__ int   g_csr[EMAX];
__device__ int   g_bsum[(NMAX + SCAN_B - 1) / SCAN_B];
__device__ int   g_boff[(NMAX + SCAN_B - 1) / SCAN_B];
__device__ int   g_gstart[64];
__device__ int   g_gend[64];
// packed bf16 hi/lo weights, fragment order: [slab8][col128][kq4] uint2
__device__ uint2 g_wh1[4096];
__device__ uint2 g_wl1[4096];
__device__ uint2 g_wh2[4096];
__device__ uint2 g_wl2[4096];

// ---------------- helpers ----------------
__device__ __forceinline__ float lrelu(float v) { return v > 0.f ? v : 0.2f * v; }
__device__ __forceinline__ float elu_f(float v) { return v > 0.f ? v : (__expf(v) - 1.f); }

__device__ __forceinline__ void split_bf(float x, float y, unsigned& hi, unsigned& lo) {
    __nv_bfloat162 h = __floats2bfloat162_rn(x, y);
    float rx = x - __bfloat162float(h.x);
    float ry = y - __bfloat162float(h.y);
    __nv_bfloat162 l = __floats2bfloat162_rn(rx, ry);
    hi = *(unsigned*)&h;
    lo = *(unsigned*)&l;
}

__device__ __forceinline__ void mma_bf16(float* d, const unsigned* a, unsigned b0, unsigned b1) {
    asm("mma.sync.aligned.m16n8k16.row.col.f32.bf16.bf16.f32 "
        "{%0,%1,%2,%3},{%4,%5,%6,%7},{%8,%9},{%0,%1,%2,%3};"
        : "+f"(d[0]), "+f"(d[1]), "+f"(d[2]), "+f"(d[3])
        : "r"(a[0]), "r"(a[1]), "r"(a[2]), "r"(a[3]), "r"(b0), "r"(b1));
}

// ---------------- init (+ graph bounds fused) ----------------
__global__ void init_kernel(int* cnt, int* gs, int* ge, const int* __restrict__ batch, int N) {
    int i = blockIdx.x * blockDim.x + threadIdx.x;
    if (i < N) {
        cnt[i] = 0;
        int b = batch[i];
        if (i == 0 || batch[i - 1] != b) gs[b] = i;
        if (i == N - 1 || batch[i + 1] != b) ge[b] = i + 1;
    }
}

// ---------------- CSR: histogram ----------------
__global__ void hist_kernel(const int* __restrict__ ei, int E, int* cnt) {
    int e = blockIdx.x * blockDim.x + threadIdx.x;
    if (e >= E) return;
    atomicAdd(cnt + ei[E + e], 1);
}

// ---------------- pack BOTH weight matrices into bf16 hi/lo fragment order ----------------
__global__ void wpack_kernel(const float* __restrict__ W1, const float* __restrict__ W2,
                             uint2* Wh1, uint2* Wl1, uint2* Wh2, uint2* Wl2) {
    int t = blockIdx.x * blockDim.x + threadIdx.x;
    if (t >= 8192) return;
    const float* W = (t < 4096) ? W1 : W2;
    uint2* Wh = (t < 4096) ? Wh1 : Wh2;
    uint2* Wl = (t < 4096) ? Wl1 : Wl2;
    int i = t & 4095;
    int kq   = i & 3;
    int col  = (i >> 2) & 127;
    int slab = i >> 9;
    int k0 = slab * 16 + 2 * kq;
    uint2 h, l;
    split_bf(W[k0 * 128 + col],       W[(k0 + 1) * 128 + col], h.x, l.x);
    split_bf(W[(k0 + 8) * 128 + col], W[(k0 + 9) * 128 + col], h.y, l.y);
    Wh[i] = h;
    Wl[i] = l;
}

// ---------------- tensor-core GEMM: C[N,128] = A[N,128] @ W[128,128], 3xBF16 ----------------
// block: 64 rows; 8 warps = 4 row-groups x 2 col-halves; warp = 16 rows x 64 cols.
template <bool ATTN>
__global__ __launch_bounds__(256, 2) void gemm_tc_kernel(const float* __restrict__ A,
                                                         const uint2* __restrict__ Wh,
                                                         const uint2* __restrict__ Wl,
                                                         float* __restrict__ C,
                                                         const float* __restrict__ att_src,
                                                         const float* __restrict__ att_dst,
                                                         float* __restrict__ asrc,
                                                         float* __restrict__ adst, int N) {
    __shared__ float As[64 * 36];        // 9216 B (stage of 32 k-cols, stride 36)
    __shared__ uint2 Bh[1024];           // 8192 B (2 slabs, all 128 cols)
    __shared__ uint2 Bl[1024];           // 8192 B

    int t = threadIdx.x;
    int warp = t >> 5, lane = t & 31;
    int g4 = lane >> 2, kq = lane & 3;
    int rg = warp >> 1;          // row group 0..3
    int ch = warp & 1;           // col half 0..1
    int wrow = rg * 16;
    int brow0 = blockIdx.x * 64;

    float acc[8][4];
    #pragma unroll
    for (int j = 0; j < 8; j++)
        #pragma unroll
        for (int q = 0; q < 4; q++) acc[j][q] = 0.f;

    #pragma unroll
    for (int stage = 0; stage < 4; stage++) {
        __syncthreads();
        // A chunk [64][32] -> smem stride 36 (512 float4, 2/thread)
        #pragma unroll
        for (int i = 0; i < 2; i++) {
            int idx = t + i * 256;
            int row = idx >> 3, c4 = idx & 7;
            float4 v = make_float4(0.f, 0.f, 0.f, 0.f);
            if (brow0 + row < N) v = ((const float4*)A)[(brow0 + row) * 32 + stage * 8 + c4];
            *(float4*)(As + row * 36 + c4 * 4) = v;
        }
        // W chunk: 1024 uint2 each (linear)
        {
            const float4* sh = (const float4*)(Wh + stage * 1024);
            const float4* sl = (const float4*)(Wl + stage * 1024);
            float4* dh = (float4*)Bh;
            float4* dl = (float4*)Bl;
            #pragma unroll
            for (int i = 0; i < 2; i++) {
                dh[t + i * 256] = sh[t + i * 256];
                dl[t + i * 256] = sl[t + i * 256];
            }
        }
        __syncthreads();

        #pragma unroll
        for (int sl = 0; sl < 2; sl++) {
            int kb = sl * 16 + 2 * kq;
            float2 A0 = *(const float2*)(As + (wrow + g4) * 36 + kb);
            float2 A1 = *(const float2*)(As + (wrow + g4) * 36 + kb + 8);
            float2 A2 = *(const float2*)(As + (wrow + g4 + 8) * 36 + kb);
            float2 A3 = *(const float2*)(As + (wrow + g4 + 8) * 36 + kb + 8);
            unsigned ah[4], al[4];
            split_bf(A0.x, A0.y, ah[0], al[0]);
            split_bf(A2.x, A2.y, ah[1], al[1]);
            split_bf(A1.x, A1.y, ah[2], al[2]);
            split_bf(A3.x, A3.y, ah[3], al[3]);
            #pragma unroll
            for (int j = 0; j < 8; j++) {
                int ct = ch * 8 + j;   // column tile 0..15
                uint2 bh = Bh[sl * 512 + (ct * 8 + g4) * 4 + kq];
                uint2 bl = Bl[sl * 512 + (ct * 8 + g4) * 4 + kq];
                mma_bf16(acc[j], ah, bh.x, bh.y);
                mma_bf16(acc[j], al, bh.x, bh.y);
                mma_bf16(acc[j], ah, bl.x, bl.y);
            }
        }
    }

    int r0 = brow0 + wrow + g4;
    #pragma unroll
    for (int j = 0; j < 8; j++) {
        int col = ch * 64 + j * 8 + kq * 2;
        if (r0 < N)     *(float2*)(C + r0 * 128 + col)       = make_float2(acc[j][0], acc[j][1]);
        if (r0 + 8 < N) *(float2*)(C + (r0 + 8) * 128 + col) = make_float2(acc[j][2], acc[j][3]);
    }

    if (ATTN) {
        // warp covers heads ch*2, ch*2+1 (32 cols each = 4 j-tiles)
        #pragma unroll
        for (int hh = 0; hh < 2; hh++) {
            int head = ch * 2 + hh;
            float psl = 0.f, psh = 0.f, pdl = 0.f, pdh = 0.f;
            #pragma unroll
            for (int jj = 0; jj < 4; jj++) {
                int j = hh * 4 + jj;
                int col = ch * 64 + j * 8 + 2 * kq;
                float2 av = *(const float2*)(att_src + col);
                float2 dv = *(const float2*)(att_dst + col);
                psl += acc[j][0] * av.x + acc[j][1] * av.y;
                psh += acc[j][2] * av.x + acc[j][3] * av.y;
                pdl += acc[j][0] * dv.x + acc[j][1] * dv.y;
                pdh += acc[j][2] * dv.x + acc[j][3] * dv.y;
            }
            psl += __shfl_xor_sync(0xffffffffu, psl, 1);
            psl += __shfl_xor_sync(0xffffffffu, psl, 2);
            psh += __shfl_xor_sync(0xffffffffu, psh, 1);
            psh += __shfl_xor_sync(0xffffffffu, psh, 2);
            pdl += __shfl_xor_sync(0xffffffffu, pdl, 1);
            pdl += __shfl_xor_sync(0xffffffffu, pdl, 2);
            pdh += __shfl_xor_sync(0xffffffffu, pdh, 1);
            pdh += __shfl_xor_sync(0xffffffffu, pdh, 2);
            if (kq == 0) {
                if (r0 < N)     { asrc[r0 * 4 + head] = psl;       adst[r0 * 4 + head] = pdl; }
                if (r0 + 8 < N) { asrc[(r0 + 8) * 4 + head] = psh; adst[(r0 + 8) * 4 + head] = pdh; }
            }
        }
    }
}

// ---------------- CSR scan ----------------
__global__ __launch_bounds__(SCAN_B) void blocksum_kernel(const int* __restrict__ cnt,
                                                          int* bsum, int N) {
    __shared__ int sh[SCAN_B];
    int i = blockIdx.x * SCAN_B + threadIdx.x;
    sh[threadIdx.x] = (i < N) ? cnt[i] : 0;
    __syncthreads();
    #pragma unroll
    for (int o = SCAN_B / 2; o; o >>= 1) {
        if (threadIdx.x < o) sh[threadIdx.x] += sh[threadIdx.x + o];
        __syncthreads();
    }
    if (threadIdx.x == 0) bsum[blockIdx.x] = sh[0];
}

__global__ __launch_bounds__(256) void bscan_kernel(const int* __restrict__ bsum,
                                                    int* boff, int NB) {
    __shared__ int sh[256];
    int t = threadIdx.x;
    sh[t] = (t < NB) ? bsum[t] : 0;
    __syncthreads();
    #pragma unroll
    for (int o = 1; o < 256; o <<= 1) {
        int v = (t >= o) ? sh[t - o] : 0;
        __syncthreads();
        sh[t] += v;
        __syncthreads();
    }
    if (t < NB) boff[t] = (t == 0) ? 0 : sh[t - 1];
}

__global__ __launch_bounds__(SCAN_B) void scanfin_kernel(const int* __restrict__ cnt,
                                                         const int* __restrict__ boff,
                                                         int* offs, int* cursor, int N, int E) {
    __shared__ int sh[SCAN_B];
    int t = threadIdx.x;
    int i = blockIdx.x * SCAN_B + t;
    int v = (i < N) ? cnt[i] : 0;
    sh[t] = v;
    __syncthreads();
    #pragma unroll
    for (int o = 1; o < SCAN_B; o <<= 1) {
        int u = (t >= o) ? sh[t - o] : 0;
        __syncthreads();
        sh[t] += u;
        __syncthreads();
    }
    if (i < N) {
        int off = boff[blockIdx.x] + sh[t] - v;
        offs[i] = off;
        cursor[i] = off;
    }
    if (i == 0) offs[N] = E;
}

__global__ void scatter_kernel(const int* __restrict__ ei, int E, int* cursor, int* csr) {
    int e = blockIdx.x * blockDim.x + threadIdx.x;
    if (e >= E) return;
    int d = ei[E + e];
    int pos = atomicAdd(cursor + d, 1);
    csr[pos] = ei[e];
}

// ---------------- GAT aggregation: warp/node, branchless 8-wide broadcast ----------------
__global__ __launch_bounds__(256) void gat_agg_kernel(const int* __restrict__ csr,
                                                      const int* __restrict__ offs,
                                                      const float* __restrict__ h,
                                                      const float* __restrict__ asrc,
                                                      const float* __restrict__ adst,
                                                      const float* __restrict__ b_gat,
                                                      const float* __restrict__ bn1w,
                                                      const float* __restrict__ bn1b,
                                                      float* __restrict__ out1,
                                                      float* __restrict__ dinv, int N) {
    int n = (blockIdx.x * 256 + threadIdx.x) >> 5;
    if (n >= N) return;
    int lane = threadIdx.x & 31;
    int hd  = lane >> 3;
    int sub = lane & 7;
    int grp = lane & 24;
    int beg = offs[n], end = offs[n + 1];

    float adn = __ldg(adst + n * 4 + hd);
    float asn = __ldg(asrc + n * 4 + hd);
    float wself = __expf(lrelu(asn + adn));

    float4 hv = *(const float4*)(h + n * 128 + lane * 4);
    float4 acc = make_float4(hv.x * wself, hv.y * wself, hv.z * wself, hv.w * wself);

    float wpart = 0.f;
    for (int c0 = beg; c0 < end; c0 += 8) {
        int e = c0 + sub;
        float w = 0.f; int s = 0;
        if (e < end) {
            s = __ldg(csr + e);
            w = __expf(lrelu(__ldg(asrc + s * 4 + hd) + adn));
        }
        wpart += w;
        #pragma unroll
        for (int i = 0; i < 8; i++) {
            int   si = __shfl_sync(0xffffffffu, s, i);
            float a  = __shfl_sync(0xffffffffu, w, grp + i);
            float4 hs = *(const float4*)(h + si * 128 + lane * 4);
            acc.x += hs.x * a; acc.y += hs.y * a; acc.z += hs.z * a; acc.w += hs.w * a;
        }
    }

    #pragma unroll
    for (int o = 1; o < 8; o <<= 1) wpart += __shfl_xor_sync(0xffffffffu, wpart, o);
    float inv = 1.f / (wpart + wself + 1e-16f);

    int c = lane * 4;
    float4 bb = *(const float4*)(b_gat + c);
    float4 w1 = *(const float4*)(bn1w + c);
    float4 b1 = *(const float4*)(bn1b + c);
    float4 v;
    v.x = elu_f(acc.x * inv + bb.x) * w1.x + b1.x;
    v.y = elu_f(acc.y * inv + bb.y) * w1.y + b1.y;
    v.z = elu_f(acc.z * inv + bb.z) * w1.z + b1.z;
    v.w = elu_f(acc.w * inv + bb.w) * w1.w + b1.w;
    *(float4*)(out1 + n * 128 + c) = v;

    if (lane == 0) dinv[n] = rsqrtf((float)(end - beg + 1));
}

// ---------------- GCN aggregation + gate: branchless 8-wide broadcast ----------------
__global__ __launch_bounds__(256) void gcn_agg_kernel(const int* __restrict__ csr,
                                                      const int* __restrict__ offs,
                                                      const float* __restrict__ h2,
                                                      const float* __restrict__ dinv,
                                                      const float* __restrict__ b_gcn,
                                                      const float* __restrict__ bn2w,
                                                      const float* __restrict__ bn2b,
                                                      const float* __restrict__ W_gate,
                                                      const float* __restrict__ b_gate,
                                                      float* __restrict__ out2,
                                                      float* __restrict__ gate, int N) {
    int n = (blockIdx.x * 256 + threadIdx.x) >> 5;
    if (n >= N) return;
    int lane = threadIdx.x & 31;
    int sub = lane & 7;
    int beg = offs[n], end = offs[n + 1];
    float dn = __ldg(dinv + n);

    float4 hv = *(const float4*)(h2 + n * 128 + lane * 4);
    float fs = dn * dn;
    float4 acc = make_float4(hv.x * fs, hv.y * fs, hv.z * fs, hv.w * fs);

    for (int c0 = beg; c0 < end; c0 += 8) {
        int e = c0 + sub;
        float f = 0.f; int s = 0;
        if (e < end) {
            s = __ldg(csr + e);
            f = __ldg(dinv + s) * dn;
        }
        #pragma unroll
        for (int i = 0; i < 8; i++) {
            int   si = __shfl_sync(0xffffffffu, s, i);
            float a  = __shfl_sync(0xffffffffu, f, i);
            float4 hs = *(const float4*)(h2 + si * 128 + lane * 4);
            acc.x += hs.x * a; acc.y += hs.y * a; acc.z += hs.z * a; acc.w += hs.w * a;
        }
    }

    int c = lane * 4;
    float4 bb = *(const float4*)(b_gcn + c);
    float4 w2 = *(const float4*)(bn2w + c);
    float4 b2 = *(const float4*)(bn2b + c);
    float4 v;
    v.x = elu_f(acc.x + bb.x) * w2.x + b2.x;
    v.y = elu_f(acc.y + bb.y) * w2.y + b2.y;
    v.z = elu_f(acc.z + bb.z) * w2.z + b2.z;
    v.w = elu_f(acc.w + bb.w) * w2.w + b2.w;
    *(float4*)(out2 + n * 128 + c) = v;

    float4 wg = *(const float4*)(W_gate + c);
    float p = v.x * wg.x + v.y * wg.y + v.z * wg.z + v.w * wg.w;
    #pragma unroll
    for (int o = 16; o; o >>= 1) p += __shfl_xor_sync(0xffffffffu, p, o);
    if (lane == 0) gate[n] = p + b_gate[0];
}

// ---------------- pooling + FC ----------------
__global__ __launch_bounds__(256) void pool_kernel(const float* __restrict__ out2,
                                                   const float* __restrict__ gate,
                                                   const int* __restrict__ gs,
                                                   const int* __restrict__ ge,
                                                   const float* __restrict__ W_fc,
                                                   const float* __restrict__ b_fc,
                                                   float* __restrict__ out) {
    int g = blockIdx.x;
    int start = gs[g], end = ge[g];
    int tid = threadIdx.x;
    __shared__ float red[256];
    __shared__ float wsh[256];

    float mx = -3.4e38f;
    for (int n = start + tid; n < end; n += 256) mx = fmaxf(mx, gate[n]);
    red[tid] = mx;
    __syncthreads();
    #pragma unroll
    for (int o = 128; o; o >>= 1) {
        if (tid < o) red[tid] = fmaxf(red[tid], red[tid + o]);
        __syncthreads();
    }
    float gmax = red[0];
    __syncthreads();

    int c = tid & 127, half = tid >> 7;
    float acc = 0.f, wloc = 0.f;
    for (int t0 = start; t0 < end; t0 += 256) {
        int tc = min(256, end - t0);
        if (tid < tc) {
            float wv = __expf(gate[t0 + tid] - gmax);
            wsh[tid] = wv;
            wloc += wv;
        }
        __syncthreads();
        for (int j = half; j < tc; j += 2)
            acc += wsh[j] * out2[(t0 + j) * 128 + c];
        __syncthreads();
    }

    red[tid] = wloc;
    __syncthreads();
    #pragma unroll
    for (int o = 128; o; o >>= 1) {
        if (tid < o) red[tid] += red[tid + o];
        __syncthreads();
    }
    float wsum = red[0];
    __syncthreads();

    red[tid] = acc;
    __syncthreads();
    float val = 0.f;
    if (tid < 128) val = (red[tid] + red[tid + 128]) / (wsum + 1e-16f) * W_fc[tid];
    __syncthreads();
    red[tid] = (tid < 128) ? val : 0.f;
    __syncthreads();
    #pragma unroll
    for (int o = 128; o; o >>= 1) {
        if (tid < o) red[tid] += red[tid + o];
        __syncthreads();
    }
    if (tid == 0) out[g] = red[0] + b_fc[0];
}

// ---------------- launch ----------------
extern "C" void kernel_launch(void* const* d_in, const int* in_sizes, int n_in,
                              void* d_out, int out_size) {
    const float* x       = (const float*)d_in[0];
    const int*   ei      = (const int*)d_in[1];
    const int*   batch   = (const int*)d_in[2];
    const float* W_gat   = (const float*)d_in[3];
    const float* att_src = (const float*)d_in[4];
    const float* att_dst = (const float*)d_in[5];
    const float* b_gat   = (const float*)d_in[6];
    const float* bn1w    = (const float*)d_in[7];
    const float* bn1b    = (const float*)d_in[8];
    const float* W_gcn   = (const float*)d_in[9];
    const float* b_gcn   = (const float*)d_in[10];
    const float* bn2w    = (const float*)d_in[11];
    const float* bn2b    = (const float*)d_in[12];
    const float* W_gate  = (const float*)d_in[13];
    const float* b_gate  = (const float*)d_in[14];
    const float* W_fc    = (const float*)d_in[15];
    const float* b_fc    = (const float*)d_in[16];
    float* out = (float*)d_out;

    int N = in_sizes[0] / 128;
    int E = in_sizes[1] / 2;
    int NB = (N + SCAN_B - 1) / SCAN_B;

    float *p_h, *p_h2, *p_asrc, *p_adst, *p_out1, *p_out2, *p_gate, *p_dinv;
    uint2 *p_wh1, *p_wl1, *p_wh2, *p_wl2;
    int *p_cnt, *p_offs, *p_cursor, *p_csr, *p_bsum, *p_boff, *p_gs, *p_ge;
    cudaGetSymbolAddress((void**)&p_h,     g_h);
    cudaGetSymbolAddress((void**)&p_h2,    g_h2);
    cudaGetSymbolAddress((void**)&p_asrc,  g_asrc);
    cudaGetSymbolAddress((void**)&p_adst,  g_adst);
    cudaGetSymbolAddress((void**)&p_out1,  g_out1);
    cudaGetSymbolAddress((void**)&p_out2,  g_out2);
    cudaGetSymbolAddress((void**)&p_gate,  g_gate);
    cudaGetSymbolAddress((void**)&p_dinv,  g_dinv);
    cudaGetSymbolAddress((void**)&p_cnt,   g_cnt);
    cudaGetSymbolAddress((void**)&p_offs,  g_offs);
    cudaGetSymbolAddress((void**)&p_cursor,g_cursor);
    cudaGetSymbolAddress((void**)&p_csr,   g_csr);
    cudaGetSymbolAddress((void**)&p_bsum,  g_bsum);
    cudaGetSymbolAddress((void**)&p_boff,  g_boff);
    cudaGetSymbolAddress((void**)&p_gs,    g_gstart);
    cudaGetSymbolAddress((void**)&p_ge,    g_gend);
    cudaGetSymbolAddress((void**)&p_wh1,   g_wh1);
    cudaGetSymbolAddress((void**)&p_wl1,   g_wl1);
    cudaGetSymbolAddress((void**)&p_wh2,   g_wh2);
    cudaGetSymbolAddress((void**)&p_wl2,   g_wl2);

    int gblk = (N + 63) / 64;

    init_kernel<<<(N + 255) / 256, 256>>>(p_cnt, p_gs, p_ge, batch, N);             // 0
    hist_kernel<<<(E + 255) / 256, 256>>>(ei, E, p_cnt);                            // 1
    wpack_kernel<<<32, 256>>>(W_gat, W_gcn, p_wh1, p_wl1, p_wh2, p_wl2);            // 2
    gemm_tc_kernel<true><<<gblk, 256>>>(x, p_wh1, p_wl1, p_h, att_src, att_dst,
                                        p_asrc, p_adst, N);                         // 3 (ncu)
    blocksum_kernel<<<NB, SCAN_B>>>(p_cnt, p_bsum, N);                              // 4
    bscan_kernel<<<1, 256>>>(p_bsum, p_boff, NB);                                   // 5
    scanfin_kernel<<<NB, SCAN_B>>>(p_cnt, p_boff, p_offs, p_cursor, N, E);          // 6
    scatter_kernel<<<(E + 255) / 256, 256>>>(ei, E, p_cursor, p_csr);               // 7
    gat_agg_kernel<<<(N * 32 + 255) / 256, 256>>>(p_csr, p_offs, p_h, p_asrc, p_adst,
                                                  b_gat, bn1w, bn1b, p_out1, p_dinv, N); // 8
    gemm_tc_kernel<false><<<gblk, 256>>>(p_out1, p_wh2, p_wl2, p_h2, nullptr, nullptr,
                                         nullptr, nullptr, N);                      // 9
    gcn_agg_kernel<<<(N * 32 + 255) / 256, 256>>>(p_csr, p_offs, p_h2, p_dinv,
                                                  b_gcn, bn2w, bn2b, W_gate, b_gate,
                                                  p_out2, p_gate, N);               // 10
    pool_kernel<<<64, 256>>>(p_out2, p_gate, p_gs, p_ge, W_fc, b_fc, out);          // 11
}

// round 12
// speedup vs baseline: 2.3484x; 1.0957x over previous
#include <cuda_runtime.h>
#include <cuda_bf16.h>
#include <cuda_fp16.h>
#include <math.h>

#define NMAX 50048
#define EMAX 800000
#define SCAN_B 256

// ---------------- scratch (device globals) ----------------
__device__ __half2 g_h[NMAX * 64];     // x @ W_gat (fp16 messages)
__device__ __half2 g_h2[NMAX * 64];    // out1 @ W_gcn (fp16 messages)
__device__ float g_asrc[NMAX * 4];
__device__ float g_adst[NMAX * 4];
__device__ float g_out1[NMAX * 128];
__device__ float g_out2[NMAX * 128];
__device__ float g_gate[NMAX];
__device__ float g_dinv[NMAX];
__device__ int   g_cnt[NMAX];
__device__ int   g_offs[NMAX + 1];
__device__ int   g_cursor[NMAX];
__device__ int   g_csr[EMAX];
__device__ int   g_bsum[(NMAX + SCAN_B - 1) / SCAN_B];
__device__ int   g_boff[(NMAX + SCAN_B - 1) / SCAN_B];
__device__ int   g_gstart[64];
__device__ int   g_gend[64];
// packed bf16 hi/lo weights, fragment order: [slab8][col128][kq4] uint2
__device__ uint2 g_wh1[4096];
__device__ uint2 g_wl1[4096];
__device__ uint2 g_wh2[4096];
__device__ uint2 g_wl2[4096];

// ---------------- helpers ----------------
__device__ __forceinline__ float lrelu(float v) { return v > 0.f ? v : 0.2f * v; }
__device__ __forceinline__ float elu_f(float v) { return v > 0.f ? v : (__expf(v) - 1.f); }

__device__ __forceinline__ void split_bf(float x, float y, unsigned& hi, unsigned& lo) {
    __nv_bfloat162 h = __floats2bfloat162_rn(x, y);
    float rx = x - __bfloat162float(h.x);
    float ry = y - __bfloat162float(h.y);
    __nv_bfloat162 l = __floats2bfloat162_rn(rx, ry);
    hi = *(unsigned*)&h;
    lo = *(unsigned*)&l;
}

__device__ __forceinline__ void mma_bf16(float* d, const unsigned* a, unsigned b0, unsigned b1) {
    asm("mma.sync.aligned.m16n8k16.row.col.f32.bf16.bf16.f32 "
        "{%0,%1,%2,%3},{%4,%5,%6,%7},{%8,%9},{%0,%1,%2,%3};"
        : "+f"(d[0]), "+f"(d[1]), "+f"(d[2]), "+f"(d[3])
        : "r"(a[0]), "r"(a[1]), "r"(a[2]), "r"(a[3]), "r"(b0), "r"(b1));
}

// ---------------- init (+ graph bounds fused) ----------------
__global__ void init_kernel(int* cnt, int* gs, int* ge, const int* __restrict__ batch, int N) {
    int i = blockIdx.x * blockDim.x + threadIdx.x;
    if (i < N) {
        cnt[i] = 0;
        int b = batch[i];
        if (i == 0 || batch[i - 1] != b) gs[b] = i;
        if (i == N - 1 || batch[i + 1] != b) ge[b] = i + 1;
    }
}

// ---------------- CSR: histogram ----------------
__global__ void hist_kernel(const int* __restrict__ ei, int E, int* cnt) {
    int e = blockIdx.x * blockDim.x + threadIdx.x;
    if (e >= E) return;
    atomicAdd(cnt + ei[E + e], 1);
}

// ---------------- pack BOTH weight matrices into bf16 hi/lo fragment order ----------------
__global__ void wpack_kernel(const float* __restrict__ W1, const float* __restrict__ W2,
                             uint2* Wh1, uint2* Wl1, uint2* Wh2, uint2* Wl2) {
    int t = blockIdx.x * blockDim.x + threadIdx.x;
    if (t >= 8192) return;
    const float* W = (t < 4096) ? W1 : W2;
    uint2* Wh = (t < 4096) ? Wh1 : Wh2;
    uint2* Wl = (t < 4096) ? Wl1 : Wl2;
    int i = t & 4095;
    int kq   = i & 3;
    int col  = (i >> 2) & 127;
    int slab = i >> 9;
    int k0 = slab * 16 + 2 * kq;
    uint2 h, l;
    split_bf(W[k0 * 128 + col],       W[(k0 + 1) * 128 + col], h.x, l.x);
    split_bf(W[(k0 + 8) * 128 + col], W[(k0 + 9) * 128 + col], h.y, l.y);
    Wh[i] = h;
    Wl[i] = l;
}

// ---------------- tensor-core GEMM: Ch[N,128](fp16) = A[N,128] @ W[128,128], 3xBF16 ----------------
// block: 64 rows; 8 warps = 4 row-groups x 2 col-halves; warp = 16 rows x 64 cols.
template <bool ATTN>
__global__ __launch_bounds__(256, 2) void gemm_tc_kernel(const float* __restrict__ A,
                                                         const uint2* __restrict__ Wh,
                                                         const uint2* __restrict__ Wl,
                                                         __half2* __restrict__ Ch,
                                                         const float* __restrict__ att_src,
                                                         const float* __restrict__ att_dst,
                                                         float* __restrict__ asrc,
                                                         float* __restrict__ adst, int N) {
    __shared__ float As[64 * 36];        // 9216 B
    __shared__ uint2 Bh[1024];           // 8192 B
    __shared__ uint2 Bl[1024];           // 8192 B

    int t = threadIdx.x;
    int warp = t >> 5, lane = t & 31;
    int g4 = lane >> 2, kq = lane & 3;
    int rg = warp >> 1;          // row group 0..3
    int ch = warp & 1;           // col half 0..1
    int wrow = rg * 16;
    int brow0 = blockIdx.x * 64;

    float acc[8][4];
    #pragma unroll
    for (int j = 0; j < 8; j++)
        #pragma unroll
        for (int q = 0; q < 4; q++) acc[j][q] = 0.f;

    #pragma unroll
    for (int stage = 0; stage < 4; stage++) {
        __syncthreads();
        #pragma unroll
        for (int i = 0; i < 2; i++) {
            int idx = t + i * 256;
            int row = idx >> 3, c4 = idx & 7;
            float4 v = make_float4(0.f, 0.f, 0.f, 0.f);
            if (brow0 + row < N) v = ((const float4*)A)[(brow0 + row) * 32 + stage * 8 + c4];
            *(float4*)(As + row * 36 + c4 * 4) = v;
        }
        {
            const float4* sh = (const float4*)(Wh + stage * 1024);
            const float4* sl = (const float4*)(Wl + stage * 1024);
            float4* dh = (float4*)Bh;
            float4* dl = (float4*)Bl;
            #pragma unroll
            for (int i = 0; i < 2; i++) {
                dh[t + i * 256] = sh[t + i * 256];
                dl[t + i * 256] = sl[t + i * 256];
            }
        }
        __syncthreads();

        #pragma unroll
        for (int sl = 0; sl < 2; sl++) {
            int kb = sl * 16 + 2 * kq;
            float2 A0 = *(const float2*)(As + (wrow + g4) * 36 + kb);
            float2 A1 = *(const float2*)(As + (wrow + g4) * 36 + kb + 8);
            float2 A2 = *(const float2*)(As + (wrow + g4 + 8) * 36 + kb);
            float2 A3 = *(const float2*)(As + (wrow + g4 + 8) * 36 + kb + 8);
            unsigned ah[4], al[4];
            split_bf(A0.x, A0.y, ah[0], al[0]);
            split_bf(A2.x, A2.y, ah[1], al[1]);
            split_bf(A1.x, A1.y, ah[2], al[2]);
            split_bf(A3.x, A3.y, ah[3], al[3]);
            #pragma unroll
            for (int j = 0; j < 8; j++) {
                int ct = ch * 8 + j;
                uint2 bh = Bh[sl * 512 + (ct * 8 + g4) * 4 + kq];
                uint2 bl = Bl[sl * 512 + (ct * 8 + g4) * 4 + kq];
                mma_bf16(acc[j], ah, bh.x, bh.y);
                mma_bf16(acc[j], al, bh.x, bh.y);
                mma_bf16(acc[j], ah, bl.x, bl.y);
            }
        }
    }

    // fp16 output: each thread stores one half2 per (j, row-half)
    int r0 = brow0 + wrow + g4;
    #pragma unroll
    for (int j = 0; j < 8; j++) {
        int hcol = ch * 32 + j * 4 + kq;   // half2 index within row
        if (r0 < N)
            Ch[r0 * 64 + hcol] = __floats2half2_rn(acc[j][0], acc[j][1]);
        if (r0 + 8 < N)
            Ch[(r0 + 8) * 64 + hcol] = __floats2half2_rn(acc[j][2], acc[j][3]);
    }

    if (ATTN) {
        #pragma unroll
        for (int hh = 0; hh < 2; hh++) {
            int head = ch * 2 + hh;
            float psl = 0.f, psh = 0.f, pdl = 0.f, pdh = 0.f;
            #pragma unroll
            for (int jj = 0; jj < 4; jj++) {
                int j = hh * 4 + jj;
                int col = ch * 64 + j * 8 + 2 * kq;
                float2 av = *(const float2*)(att_src + col);
                float2 dv = *(const float2*)(att_dst + col);
                psl += acc[j][0] * av.x + acc[j][1] * av.y;
                psh += acc[j][2] * av.x + acc[j][3] * av.y;
                pdl += acc[j][0] * dv.x + acc[j][1] * dv.y;
                pdh += acc[j][2] * dv.x + acc[j][3] * dv.y;
            }
            psl += __shfl_xor_sync(0xffffffffu, psl, 1);
            psl += __shfl_xor_sync(0xffffffffu, psl, 2);
            psh += __shfl_xor_sync(0xffffffffu, psh, 1);
            psh += __shfl_xor_sync(0xffffffffu, psh, 2);
            pdl += __shfl_xor_sync(0xffffffffu, pdl, 1);
            pdl += __shfl_xor_sync(0xffffffffu, pdl, 2);
            pdh += __shfl_xor_sync(0xffffffffu, pdh, 1);
            pdh += __shfl_xor_sync(0xffffffffu, pdh, 2);
            if (kq == 0) {
                if (r0 < N)     { asrc[r0 * 4 + head] = psl;       adst[r0 * 4 + head] = pdl; }
                if (r0 + 8 < N) { asrc[(r0 + 8) * 4 + head] = psh; adst[(r0 + 8) * 4 + head] = pdh; }
            }
        }
    }
}

// ---------------- CSR scan ----------------
__global__ __launch_bounds__(SCAN_B) void blocksum_kernel(const int* __restrict__ cnt,
                                                          int* bsum, int N) {
    __shared__ int sh[SCAN_B];
    int i = blockIdx.x * SCAN_B + threadIdx.x;
    sh[threadIdx.x] = (i < N) ? cnt[i] : 0;
    __syncthreads();
    #pragma unroll
    for (int o = SCAN_B / 2; o; o >>= 1) {
        if (threadIdx.x < o) sh[threadIdx.x] += sh[threadIdx.x + o];
        __syncthreads();
    }
    if (threadIdx.x == 0) bsum[blockIdx.x] = sh[0];
}

__global__ __launch_bounds__(256) void bscan_kernel(const int* __restrict__ bsum,
                                                    int* boff, int NB) {
    __shared__ int sh[256];
    int t = threadIdx.x;
    sh[t] = (t < NB) ? bsum[t] : 0;
    __syncthreads();
    #pragma unroll
    for (int o = 1; o < 256; o <<= 1) {
        int v = (t >= o) ? sh[t - o] : 0;
        __syncthreads();
        sh[t] += v;
        __syncthreads();
    }
    if (t < NB) boff[t] = (t == 0) ? 0 : sh[t - 1];
}

__global__ __launch_bounds__(SCAN_B) void scanfin_kernel(const int* __restrict__ cnt,
                                                         const int* __restrict__ boff,
                                                         int* offs, int* cursor, int N, int E) {
    __shared__ int sh[SCAN_B];
    int t = threadIdx.x;
    int i = blockIdx.x * SCAN_B + t;
    int v = (i < N) ? cnt[i] : 0;
    sh[t] = v;
    __syncthreads();
    #pragma unroll
    for (int o = 1; o < SCAN_B; o <<= 1) {
        int u = (t >= o) ? sh[t - o] : 0;
        __syncthreads();
        sh[t] += u;
        __syncthreads();
    }
    if (i < N) {
        int off = boff[blockIdx.x] + sh[t] - v;
        offs[i] = off;
        cursor[i] = off;
    }
    if (i == 0) offs[N] = E;
}

__global__ void scatter_kernel(const int* __restrict__ ei, int E, int* cursor, int* csr) {
    int e = blockIdx.x * blockDim.x + threadIdx.x;
    if (e >= E) return;
    int d = ei[E + e];
    int pos = atomicAdd(cursor + d, 1);
    csr[pos] = ei[e];
}

// ---------------- GAT aggregation: warp/node, branchless, fp16 gathers ----------------
__global__ __launch_bounds__(256) void gat_agg_kernel(const int* __restrict__ csr,
                                                      const int* __restrict__ offs,
                                                      const __half2* __restrict__ h,
                                                      const float* __restrict__ asrc,
                                                      const float* __restrict__ adst,
                                                      const float* __restrict__ b_gat,
                                                      const float* __restrict__ bn1w,
                                                      const float* __restrict__ bn1b,
                                                      float* __restrict__ out1,
                                                      float* __restrict__ dinv, int N) {
    int n = (blockIdx.x * 256 + threadIdx.x) >> 5;
    if (n >= N) return;
    int lane = threadIdx.x & 31;
    int hd  = lane >> 3;
    int sub = lane & 7;
    int grp = lane & 24;
    int beg = offs[n], end = offs[n + 1];

    float adn = __ldg(adst + n * 4 + hd);
    float asn = __ldg(asrc + n * 4 + hd);
    float wself = __expf(lrelu(asn + adn));

    uint2 us = __ldg((const uint2*)(h + n * 64 + lane * 2));
    float2 h0 = __half22float2(*(__half2*)&us.x);
    float2 h1 = __half22float2(*(__half2*)&us.y);
    float4 acc = make_float4(h0.x * wself, h0.y * wself, h1.x * wself, h1.y * wself);

    float wpart = 0.f;
    for (int c0 = beg; c0 < end; c0 += 8) {
        int e = c0 + sub;
        float w = 0.f; int s = 0;
        if (e < end) {
            s = __ldg(csr + e);
            w = __expf(lrelu(__ldg(asrc + s * 4 + hd) + adn));
        }
        wpart += w;
        #pragma unroll
        for (int i = 0; i < 8; i++) {
            int   si = __shfl_sync(0xffffffffu, s, i);
            float a  = __shfl_sync(0xffffffffu, w, grp + i);
            uint2 u = __ldg((const uint2*)(h + si * 64 + lane * 2));
            float2 g0 = __half22float2(*(__half2*)&u.x);
            float2 g1 = __half22float2(*(__half2*)&u.y);
            acc.x += g0.x * a; acc.y += g0.y * a;
            acc.z += g1.x * a; acc.w += g1.y * a;
        }
    }

    #pragma unroll
    for (int o = 1; o < 8; o <<= 1) wpart += __shfl_xor_sync(0xffffffffu, wpart, o);
    float inv = 1.f / (wpart + wself + 1e-16f);

    int c = lane * 4;
    float4 bb = *(const float4*)(b_gat + c);
    float4 w1 = *(const float4*)(bn1w + c);
    float4 b1 = *(const float4*)(bn1b + c);
    float4 v;
    v.x = elu_f(acc.x * inv + bb.x) * w1.x + b1.x;
    v.y = elu_f(acc.y * inv + bb.y) * w1.y + b1.y;
    v.z = elu_f(acc.z * inv + bb.z) * w1.z + b1.z;
    v.w = elu_f(acc.w * inv + bb.w) * w1.w + b1.w;
    *(float4*)(out1 + n * 128 + c) = v;

    if (lane == 0) dinv[n] = rsqrtf((float)(end - beg + 1));
}

// ---------------- GCN aggregation + gate: branchless, fp16 gathers ----------------
__global__ __launch_bounds__(256) void gcn_agg_kernel(const int* __restrict__ csr,
                                                      const int* __restrict__ offs,
                                                      const __half2* __restrict__ h2,
                                                      const float* __restrict__ dinv,
                                                      const float* __restrict__ b_gcn,
                                                      const float* __restrict__ bn2w,
                                                      const float* __restrict__ bn2b,
                                                      const float* __restrict__ W_gate,
                                                      const float* __restrict__ b_gate,
                                                      float* __restrict__ out2,
                                                      float* __restrict__ gate, int N) {
    int n = (blockIdx.x * 256 + threadIdx.x) >> 5;
    if (n >= N) return;
    int lane = threadIdx.x & 31;
    int sub = lane & 7;
    int beg = offs[n], end = offs[n + 1];
    float dn = __ldg(dinv + n);

    uint2 us = __ldg((const uint2*)(h2 + n * 64 + lane * 2));
    float2 h0 = __half22float2(*(__half2*)&us.x);
    float2 h1 = __half22float2(*(__half2*)&us.y);
    float fs = dn * dn;
    float4 acc = make_float4(h0.x * fs, h0.y * fs, h1.x * fs, h1.y * fs);

    for (int c0 = beg; c0 < end; c0 += 8) {
        int e = c0 + sub;
        float f = 0.f; int s = 0;
        if (e < end) {
            s = __ldg(csr + e);
            f = __ldg(dinv + s) * dn;
        }
        #pragma unroll
        for (int i = 0; i < 8; i++) {
            int   si = __shfl_sync(0xffffffffu, s, i);
            float a  = __shfl_sync(0xffffffffu, f, i);
            uint2 u = __ldg((const uint2*)(h2 + si * 64 + lane * 2));
            float2 g0 = __half22float2(*(__half2*)&u.x);
            float2 g1 = __half22float2(*(__half2*)&u.y);
            acc.x += g0.x * a; acc.y += g0.y * a;
            acc.z += g1.x * a; acc.w += g1.y * a;
        }
    }

    int c = lane * 4;
    float4 bb = *(const float4*)(b_gcn + c);
    float4 w2 = *(const float4*)(bn2w + c);
    float4 b2 = *(const float4*)(bn2b + c);
    float4 v;
    v.x = elu_f(acc.x + bb.x) * w2.x + b2.x;
    v.y = elu_f(acc.y + bb.y) * w2.y + b2.y;
    v.z = elu_f(acc.z + bb.z) * w2.z + b2.z;
    v.w = elu_f(acc.w + bb.w) * w2.w + b2.w;
    *(float4*)(out2 + n * 128 + c) = v;

    float4 wg = *(const float4*)(W_gate + c);
    float p = v.x * wg.x + v.y * wg.y + v.z * wg.z + v.w * wg.w;
    #pragma unroll
    for (int o = 16; o; o >>= 1) p += __shfl_xor_sync(0xffffffffu, p, o);
    if (lane == 0) gate[n] = p + b_gate[0];
}

// ---------------- pooling + FC ----------------
__global__ __launch_bounds__(256) void pool_kernel(const float* __restrict__ out2,
                                                   const float* __restrict__ gate,
                                                   const int* __restrict__ gs,
                                                   const int* __restrict__ ge,
                                                   const float* __restrict__ W_fc,
                                                   const float* __restrict__ b_fc,
                                                   float* __restrict__ out) {
    int g = blockIdx.x;
    int start = gs[g], end = ge[g];
    int tid = threadIdx.x;
    __shared__ float red[256];
    __shared__ float wsh[256];

    float mx = -3.4e38f;
    for (int n = start + tid; n < end; n += 256) mx = fmaxf(mx, gate[n]);
    red[tid] = mx;
    __syncthreads();
    #pragma unroll
    for (int o = 128; o; o >>= 1) {
        if (tid < o) red[tid] = fmaxf(red[tid], red[tid + o]);
        __syncthreads();
    }
    float gmax = red[0];
    __syncthreads();

    int c = tid & 127, half = tid >> 7;
    float acc = 0.f, wloc = 0.f;
    for (int t0 = start; t0 < end; t0 += 256) {
        int tc = min(256, end - t0);
        if (tid < tc) {
            float wv = __expf(gate[t0 + tid] - gmax);
            wsh[tid] = wv;
            wloc += wv;
        }
        __syncthreads();
        for (int j = half; j < tc; j += 2)
            acc += wsh[j] * out2[(t0 + j) * 128 + c];
        __syncthreads();
    }

    red[tid] = wloc;
    __syncthreads();
    #pragma unroll
    for (int o = 128; o; o >>= 1) {
        if (tid < o) red[tid] += red[tid + o];
        __syncthreads();
    }
    float wsum = red[0];
    __syncthreads();

    red[tid] = acc;
    __syncthreads();
    float val = 0.f;
    if (tid < 128) val = (red[tid] + red[tid + 128]) / (wsum + 1e-16f) * W_fc[tid];
    __syncthreads();
    red[tid] = (tid < 128) ? val : 0.f;
    __syncthreads();
    #pragma unroll
    for (int o = 128; o; o >>= 1) {
        if (tid < o) red[tid] += red[tid + o];
        __syncthreads();
    }
    if (tid == 0) out[g] = red[0] + b_fc[0];
}

// ---------------- launch ----------------
extern "C" void kernel_launch(void* const* d_in, const int* in_sizes, int n_in,
                              void* d_out, int out_size) {
    const float* x       = (const float*)d_in[0];
    const int*   ei      = (const int*)d_in[1];
    const int*   batch   = (const int*)d_in[2];
    const float* W_gat   = (const float*)d_in[3];
    const float* att_src = (const float*)d_in[4];
    const float* att_dst = (const float*)d_in[5];
    const float* b_gat   = (const float*)d_in[6];
    const float* bn1w    = (const float*)d_in[7];
    const float* bn1b    = (const float*)d_in[8];
    const float* W_gcn   = (const float*)d_in[9];
    const float* b_gcn   = (const float*)d_in[10];
    const float* bn2w    = (const float*)d_in[11];
    const float* bn2b    = (const float*)d_in[12];
    const float* W_gate  = (const float*)d_in[13];
    const float* b_gate  = (const float*)d_in[14];
    const float* W_fc    = (const float*)d_in[15];
    const float* b_fc    = (const float*)d_in[16];
    float* out = (float*)d_out;

    int N = in_sizes[0] / 128;
    int E = in_sizes[1] / 2;
    int NB = (N + SCAN_B - 1) / SCAN_B;

    float *p_asrc, *p_adst, *p_out1, *p_out2, *p_gate, *p_dinv;
    __half2 *p_h, *p_h2;
    uint2 *p_wh1, *p_wl1, *p_wh2, *p_wl2;
    int *p_cnt, *p_offs, *p_cursor, *p_csr, *p_bsum, *p_boff, *p_gs, *p_ge;
    cudaGetSymbolAddress((void**)&p_h,     g_h);
    cudaGetSymbolAddress((void**)&p_h2,    g_h2);
    cudaGetSymbolAddress((void**)&p_asrc,  g_asrc);
    cudaGetSymbolAddress((void**)&p_adst,  g_adst);
    cudaGetSymbolAddress((void**)&p_out1,  g_out1);
    cudaGetSymbolAddress((void**)&p_out2,  g_out2);
    cudaGetSymbolAddress((void**)&p_gate,  g_gate);
    cudaGetSymbolAddress((void**)&p_dinv,  g_dinv);
    cudaGetSymbolAddress((void**)&p_cnt,   g_cnt);
    cudaGetSymbolAddress((void**)&p_offs,  g_offs);
    cudaGetSymbolAddress((void**)&p_cursor,g_cursor);
    cudaGetSymbolAddress((void**)&p_csr,   g_csr);
    cudaGetSymbolAddress((void**)&p_bsum,  g_bsum);
    cudaGetSymbolAddress((void**)&p_boff,  g_boff);
    cudaGetSymbolAddress((void**)&p_gs,    g_gstart);
    cudaGetSymbolAddress((void**)&p_ge,    g_gend);
    cudaGetSymbolAddress((void**)&p_wh1,   g_wh1);
    cudaGetSymbolAddress((void**)&p_wl1,   g_wl1);
    cudaGetSymbolAddress((void**)&p_wh2,   g_wh2);
    cudaGetSymbolAddress((void**)&p_wl2,   g_wl2);

    int gblk = (N + 63) / 64;

    init_kernel<<<(N + 255) / 256, 256>>>(p_cnt, p_gs, p_ge, batch, N);             // 0
    hist_kernel<<<(E + 255) / 256, 256>>>(ei, E, p_cnt);                            // 1
    wpack_kernel<<<32, 256>>>(W_gat, W_gcn, p_wh1, p_wl1, p_wh2, p_wl2);            // 2
    gemm_tc_kernel<true><<<gblk, 256>>>(x, p_wh1, p_wl1, p_h, att_src, att_dst,
                                        p_asrc, p_adst, N);                         // 3 (ncu)
    blocksum_kernel<<<NB, SCAN_B>>>(p_cnt, p_bsum, N);                              // 4
    bscan_kernel<<<1, 256>>>(p_bsum, p_boff, NB);                                   // 5
    scanfin_kernel<<<NB, SCAN_B>>>(p_cnt, p_boff, p_offs, p_cursor, N, E);          // 6
    scatter_kernel<<<(E + 255) / 256, 256>>>(ei, E, p_cursor, p_csr);               // 7
    gat_agg_kernel<<<(N * 32 + 255) / 256, 256>>>(p_csr, p_offs, p_h, p_asrc, p_adst,
                                                  b_gat, bn1w, bn1b, p_out1, p_dinv, N); // 8
    gemm_tc_kernel<false><<<gblk, 256>>>(p_out1, p_wh2, p_wl2, p_h2, nullptr, nullptr,
                                         nullptr, nullptr, N);                      // 9
    gcn_agg_kernel<<<(N * 32 + 255) / 256, 256>>>(p_csr, p_offs, p_h2, p_dinv,
                                                  b_gcn, bn2w, bn2b, W_gate, b_gate,
                                                  p_out2, p_gate, N);               // 10
    pool_kernel<<<64, 256>>>(p_out2, p_gate, p_gs, p_ge, W_fc, b_fc, out);          // 11
}

// round 13
// speedup vs baseline: 2.3617x; 1.0057x over previous
#include <cuda_runtime.h>
#include <cuda_bf16.h>
#include <cuda_fp16.h>
#include <math.h>

#define NMAX 50048
#define EMAX 800000
#define SCAN_B 256

// ---------------- scratch (device globals) ----------------
__device__ __half2 g_h[NMAX * 64];     // x @ W_gat (fp16 messages)
__device__ __half2 g_h2[NMAX * 64];    // out1 @ W_gcn (fp16 messages)
__device__ float g_asrc[NMAX * 4];
__device__ float g_adst[NMAX * 4];
__device__ float g_out1[NMAX * 128];
__device__ float g_out2[NMAX * 128];
__device__ float g_gate[NMAX];
__device__ float g_dinv[NMAX];
__device__ int   g_cnt[NMAX];
__device__ int   g_offs[NMAX + 1];
__device__ int   g_cursor[NMAX];
__device__ int   g_csr[EMAX];
__device__ int   g_bsum[(NMAX + SCAN_B - 1) / SCAN_B];
__device__ int   g_boff[(NMAX + SCAN_B - 1) / SCAN_B];
__device__ int   g_gstart[64];
__device__ int   g_gend[64];
// packed bf16 hi/lo weights, fragment order: [slab8][col128][kq4] uint2
__device__ uint2 g_wh1[4096];
__device__ uint2 g_wl1[4096];
__device__ uint2 g_wh2[4096];
__device__ uint2 g_wl2[4096];

// ---------------- helpers ----------------
__device__ __forceinline__ float lrelu(float v) { return v > 0.f ? v : 0.2f * v; }
__device__ __forceinline__ float elu_f(float v) { return v > 0.f ? v : (__expf(v) - 1.f); }

__device__ __forceinline__ void split_bf(float x, float y, unsigned& hi, unsigned& lo) {
    __nv_bfloat162 h = __floats2bfloat162_rn(x, y);
    float rx = x - __bfloat162float(h.x);
    float ry = y - __bfloat162float(h.y);
    __nv_bfloat162 l = __floats2bfloat162_rn(rx, ry);
    hi = *(unsigned*)&h;
    lo = *(unsigned*)&l;
}

__device__ __forceinline__ void mma_bf16(float* d, const unsigned* a, unsigned b0, unsigned b1) {
    asm("mma.sync.aligned.m16n8k16.row.col.f32.bf16.bf16.f32 "
        "{%0,%1,%2,%3},{%4,%5,%6,%7},{%8,%9},{%0,%1,%2,%3};"
        : "+f"(d[0]), "+f"(d[1]), "+f"(d[2]), "+f"(d[3])
        : "r"(a[0]), "r"(a[1]), "r"(a[2]), "r"(a[3]), "r"(b0), "r"(b1));
}

// ---------------- init (+ graph bounds fused) ----------------
__global__ void init_kernel(int* cnt, int* gs, int* ge, const int* __restrict__ batch, int N) {
    int i = blockIdx.x * blockDim.x + threadIdx.x;
    if (i < N) {
        cnt[i] = 0;
        int b = batch[i];
        if (i == 0 || batch[i - 1] != b) gs[b] = i;
        if (i == N - 1 || batch[i + 1] != b) ge[b] = i + 1;
    }
}

// ---------------- CSR: histogram ----------------
__global__ void hist_kernel(const int* __restrict__ ei, int E, int* cnt) {
    int e = blockIdx.x * blockDim.x + threadIdx.x;
    if (e >= E) return;
    atomicAdd(cnt + ei[E + e], 1);
}

// ---------------- pack BOTH weight matrices into bf16 hi/lo fragment order ----------------
__global__ void wpack_kernel(const float* __restrict__ W1, const float* __restrict__ W2,
                             uint2* Wh1, uint2* Wl1, uint2* Wh2, uint2* Wl2) {
    int t = blockIdx.x * blockDim.x + threadIdx.x;
    if (t >= 8192) return;
    const float* W = (t < 4096) ? W1 : W2;
    uint2* Wh = (t < 4096) ? Wh1 : Wh2;
    uint2* Wl = (t < 4096) ? Wl1 : Wl2;
    int i = t & 4095;
    int kq   = i & 3;
    int col  = (i >> 2) & 127;
    int slab = i >> 9;
    int k0 = slab * 16 + 2 * kq;
    uint2 h, l;
    split_bf(W[k0 * 128 + col],       W[(k0 + 1) * 128 + col], h.x, l.x);
    split_bf(W[(k0 + 8) * 128 + col], W[(k0 + 9) * 128 + col], h.y, l.y);
    Wh[i] = h;
    Wl[i] = l;
}

// ---------------- tensor-core GEMM: Ch[N,128](fp16) = A[N,128] @ W[128,128], 3xBF16 ----------------
// block: 64 rows; 8 warps = 4 row-groups x 2 col-halves; warp = 16 rows x 64 cols.
// Double-buffered smem staging: one __syncthreads per stage, loads overlap compute.
template <bool ATTN>
__global__ __launch_bounds__(256, 2) void gemm_tc_kernel(const float* __restrict__ A,
                                                         const uint2* __restrict__ Wh,
                                                         const uint2* __restrict__ Wl,
                                                         __half2* __restrict__ Ch,
                                                         const float* __restrict__ att_src,
                                                         const float* __restrict__ att_dst,
                                                         float* __restrict__ asrc,
                                                         float* __restrict__ adst, int N) {
    __shared__ float As[2][64 * 36];     // 18432 B
    __shared__ uint2 Bh[2][1024];        // 16384 B
    __shared__ uint2 Bl[2][1024];        // 16384 B   (total 51200 B, 2 blocks/SM)

    int t = threadIdx.x;
    int warp = t >> 5, lane = t & 31;
    int g4 = lane >> 2, kq = lane & 3;
    int rg = warp >> 1;          // row group 0..3
    int ch = warp & 1;           // col half 0..1
    int wrow = rg * 16;
    int brow0 = blockIdx.x * 64;

    // per-thread staging indices
    int arow0 = t >> 3, ac4 = t & 7;          // A: 2 rows (t, t+256 pattern)
    int arow1 = (t + 256) >> 3;

    float acc[8][4];
    #pragma unroll
    for (int j = 0; j < 8; j++)
        #pragma unroll
        for (int q = 0; q < 4; q++) acc[j][q] = 0.f;

    // prologue: stage 0 -> buffer 0
    {
        float4 va0 = make_float4(0.f, 0.f, 0.f, 0.f);
        float4 va1 = make_float4(0.f, 0.f, 0.f, 0.f);
        if (brow0 + arow0 < N) va0 = ((const float4*)A)[(brow0 + arow0) * 32 + ac4];
        if (brow0 + arow1 < N) va1 = ((const float4*)A)[(brow0 + arow1) * 32 + ac4];
        float4 vh0 = ((const float4*)Wh)[t];
        float4 vh1 = ((const float4*)Wh)[t + 256];
        float4 vl0 = ((const float4*)Wl)[t];
        float4 vl1 = ((const float4*)Wl)[t + 256];
        *(float4*)(As[0] + arow0 * 36 + ac4 * 4) = va0;
        *(float4*)(As[0] + arow1 * 36 + ac4 * 4) = va1;
        ((float4*)Bh[0])[t] = vh0;
        ((float4*)Bh[0])[t + 256] = vh1;
        ((float4*)Bl[0])[t] = vl0;
        ((float4*)Bl[0])[t + 256] = vl1;
    }
    __syncthreads();

    #pragma unroll
    for (int stage = 0; stage < 4; stage++) {
        int cur = stage & 1, nxt = cur ^ 1;

        // issue next-stage loads early (overlap with compute)
        float4 va0, va1, vh0, vh1, vl0, vl1;
        if (stage < 3) {
            int s1 = stage + 1;
            va0 = make_float4(0.f, 0.f, 0.f, 0.f);
            va1 = make_float4(0.f, 0.f, 0.f, 0.f);
            if (brow0 + arow0 < N) va0 = ((const float4*)A)[(brow0 + arow0) * 32 + s1 * 8 + ac4];
            if (brow0 + arow1 < N) va1 = ((const float4*)A)[(brow0 + arow1) * 32 + s1 * 8 + ac4];
            vh0 = ((const float4*)Wh)[s1 * 512 + t];
            vh1 = ((const float4*)Wh)[s1 * 512 + t + 256];
            vl0 = ((const float4*)Wl)[s1 * 512 + t];
            vl1 = ((const float4*)Wl)[s1 * 512 + t + 256];
        }

        // compute current stage
        #pragma unroll
        for (int sl = 0; sl < 2; sl++) {
            int kb = sl * 16 + 2 * kq;
            float2 A0 = *(const float2*)(As[cur] + (wrow + g4) * 36 + kb);
            float2 A1 = *(const float2*)(As[cur] + (wrow + g4) * 36 + kb + 8);
            float2 A2 = *(const float2*)(As[cur] + (wrow + g4 + 8) * 36 + kb);
            float2 A3 = *(const float2*)(As[cur] + (wrow + g4 + 8) * 36 + kb + 8);
            unsigned ah[4], al[4];
            split_bf(A0.x, A0.y, ah[0], al[0]);
            split_bf(A2.x, A2.y, ah[1], al[1]);
            split_bf(A1.x, A1.y, ah[2], al[2]);
            split_bf(A3.x, A3.y, ah[3], al[3]);
            #pragma unroll
            for (int j = 0; j < 8; j++) {
                int ct = ch * 8 + j;
                uint2 bh = Bh[cur][sl * 512 + (ct * 8 + g4) * 4 + kq];
                uint2 bl = Bl[cur][sl * 512 + (ct * 8 + g4) * 4 + kq];
                mma_bf16(acc[j], ah, bh.x, bh.y);
                mma_bf16(acc[j], al, bh.x, bh.y);
                mma_bf16(acc[j], ah, bl.x, bl.y);
            }
        }

        // store prefetched data into alternate buffer, then one sync
        if (stage < 3) {
            *(float4*)(As[nxt] + arow0 * 36 + ac4 * 4) = va0;
            *(float4*)(As[nxt] + arow1 * 36 + ac4 * 4) = va1;
            ((float4*)Bh[nxt])[t] = vh0;
            ((float4*)Bh[nxt])[t + 256] = vh1;
            ((float4*)Bl[nxt])[t] = vl0;
            ((float4*)Bl[nxt])[t + 256] = vl1;
            __syncthreads();
        }
    }

    // fp16 output: each thread stores one half2 per (j, row-half)
    int r0 = brow0 + wrow + g4;
    #pragma unroll
    for (int j = 0; j < 8; j++) {
        int hcol = ch * 32 + j * 4 + kq;   // half2 index within row
        if (r0 < N)
            Ch[r0 * 64 + hcol] = __floats2half2_rn(acc[j][0], acc[j][1]);
        if (r0 + 8 < N)
            Ch[(r0 + 8) * 64 + hcol] = __floats2half2_rn(acc[j][2], acc[j][3]);
    }

    if (ATTN) {
        #pragma unroll
        for (int hh = 0; hh < 2; hh++) {
            int head = ch * 2 + hh;
            float psl = 0.f, psh = 0.f, pdl = 0.f, pdh = 0.f;
            #pragma unroll
            for (int jj = 0; jj < 4; jj++) {
                int j = hh * 4 + jj;
                int col = ch * 64 + j * 8 + 2 * kq;
                float2 av = *(const float2*)(att_src + col);
                float2 dv = *(const float2*)(att_dst + col);
                psl += acc[j][0] * av.x + acc[j][1] * av.y;
                psh += acc[j][2] * av.x + acc[j][3] * av.y;
                pdl += acc[j][0] * dv.x + acc[j][1] * dv.y;
                pdh += acc[j][2] * dv.x + acc[j][3] * dv.y;
            }
            psl += __shfl_xor_sync(0xffffffffu, psl, 1);
            psl += __shfl_xor_sync(0xffffffffu, psl, 2);
            psh += __shfl_xor_sync(0xffffffffu, psh, 1);
            psh += __shfl_xor_sync(0xffffffffu, psh, 2);
            pdl += __shfl_xor_sync(0xffffffffu, pdl, 1);
            pdl += __shfl_xor_sync(0xffffffffu, pdl, 2);
            pdh += __shfl_xor_sync(0xffffffffu, pdh, 1);
            pdh += __shfl_xor_sync(0xffffffffu, pdh, 2);
            if (kq == 0) {
                if (r0 < N)     { asrc[r0 * 4 + head] = psl;       adst[r0 * 4 + head] = pdl; }
                if (r0 + 8 < N) { asrc[(r0 + 8) * 4 + head] = psh; adst[(r0 + 8) * 4 + head] = pdh; }
            }
        }
    }
}

// ---------------- CSR scan ----------------
__global__ __launch_bounds__(SCAN_B) void blocksum_kernel(const int* __restrict__ cnt,
                                                          int* bsum, int N) {
    __shared__ int sh[SCAN_B];
    int i = blockIdx.x * SCAN_B + threadIdx.x;
    sh[threadIdx.x] = (i < N) ? cnt[i] : 0;
    __syncthreads();
    #pragma unroll
    for (int o = SCAN_B / 2; o; o >>= 1) {
        if (threadIdx.x < o) sh[threadIdx.x] += sh[threadIdx.x + o];
        __syncthreads();
    }
    if (threadIdx.x == 0) bsum[blockIdx.x] = sh[0];
}

__global__ __launch_bounds__(256) void bscan_kernel(const int* __restrict__ bsum,
                                                    int* boff, int NB) {
    __shared__ int sh[256];
    int t = threadIdx.x;
    sh[t] = (t < NB) ? bsum[t] : 0;
    __syncthreads();
    #pragma unroll
    for (int o = 1; o < 256; o <<= 1) {
        int v = (t >= o) ? sh[t - o] : 0;
        __syncthreads();
        sh[t] += v;
        __syncthreads();
    }
    if (t < NB) boff[t] = (t == 0) ? 0 : sh[t - 1];
}

__global__ __launch_bounds__(SCAN_B) void scanfin_kernel(const int* __restrict__ cnt,
                                                         const int* __restrict__ boff,
                                                         int* offs, int* cursor, int N, int E) {
    __shared__ int sh[SCAN_B];
    int t = threadIdx.x;
    int i = blockIdx.x * SCAN_B + t;
    int v = (i < N) ? cnt[i] : 0;
    sh[t] = v;
    __syncthreads();
    #pragma unroll
    for (int o = 1; o < SCAN_B; o <<= 1) {
        int u = (t >= o) ? sh[t - o] : 0;
        __syncthreads();
        sh[t] += u;
        __syncthreads();
    }
    if (i < N) {
        int off = boff[blockIdx.x] + sh[t] - v;
        offs[i] = off;
        cursor[i] = off;
    }
    if (i == 0) offs[N] = E;
}

__global__ void scatter_kernel(const int* __restrict__ ei, int E, int* cursor, int* csr) {
    int e = blockIdx.x * blockDim.x + threadIdx.x;
    if (e >= E) return;
    int d = ei[E + e];
    int pos = atomicAdd(cursor + d, 1);
    csr[pos] = ei[e];
}

// ---------------- GAT aggregation: warp/node, branchless, fp16 gathers ----------------
__global__ __launch_bounds__(256) void gat_agg_kernel(const int* __restrict__ csr,
                                                      const int* __restrict__ offs,
                                                      const __half2* __restrict__ h,
                                                      const float* __restrict__ asrc,
                                                      const float* __restrict__ adst,
                                                      const float* __restrict__ b_gat,
                                                      const float* __restrict__ bn1w,
                                                      const float* __restrict__ bn1b,
                                                      float* __restrict__ out1,
                                                      float* __restrict__ dinv, int N) {
    int n = (blockIdx.x * 256 + threadIdx.x) >> 5;
    if (n >= N) return;
    int lane = threadIdx.x & 31;
    int hd  = lane >> 3;
    int sub = lane & 7;
    int grp = lane & 24;
    int beg = offs[n], end = offs[n + 1];

    float adn = __ldg(adst + n * 4 + hd);
    float asn = __ldg(asrc + n * 4 + hd);
    float wself = __expf(lrelu(asn + adn));

    uint2 us = __ldg((const uint2*)(h + n * 64 + lane * 2));
    float2 h0 = __half22float2(*(__half2*)&us.x);
    float2 h1 = __half22float2(*(__half2*)&us.y);
    float4 acc = make_float4(h0.x * wself, h0.y * wself, h1.x * wself, h1.y * wself);

    float wpart = 0.f;
    for (int c0 = beg; c0 < end; c0 += 8) {
        int e = c0 + sub;
        float w = 0.f; int s = 0;
        if (e < end) {
            s = __ldg(csr + e);
            w = __expf(lrelu(__ldg(asrc + s * 4 + hd) + adn));
        }
        wpart += w;
        #pragma unroll
        for (int i = 0; i < 8; i++) {
            int   si = __shfl_sync(0xffffffffu, s, i);
            float a  = __shfl_sync(0xffffffffu, w, grp + i);
            uint2 u = __ldg((const uint2*)(h + si * 64 + lane * 2));
            float2 g0 = __half22float2(*(__half2*)&u.x);
            float2 g1 = __half22float2(*(__half2*)&u.y);
            acc.x += g0.x * a; acc.y += g0.y * a;
            acc.z += g1.x * a; acc.w += g1.y * a;
        }
    }

    #pragma unroll
    for (int o = 1; o < 8; o <<= 1) wpart += __shfl_xor_sync(0xffffffffu, wpart, o);
    float inv = 1.f / (wpart + wself + 1e-16f);

    int c = lane * 4;
    float4 bb = *(const float4*)(b_gat + c);
    float4 w1 = *(const float4*)(bn1w + c);
    float4 b1 = *(const float4*)(bn1b + c);
    float4 v;
    v.x = elu_f(acc.x * inv + bb.x) * w1.x + b1.x;
    v.y = elu_f(acc.y * inv + bb.y) * w1.y + b1.y;
    v.z = elu_f(acc.z * inv + bb.z) * w1.z + b1.z;
    v.w = elu_f(acc.w * inv + bb.w) * w1.w + b1.w;
    *(float4*)(out1 + n * 128 + c) = v;

    if (lane == 0) dinv[n] = rsqrtf((float)(end - beg + 1));
}

// ---------------- GCN aggregation + gate: branchless, fp16 gathers ----------------
__global__ __launch_bounds__(256) void gcn_agg_kernel(const int* __restrict__ csr,
                                                      const int* __restrict__ offs,
                                                      const __half2* __restrict__ h2,
                                                      const float* __restrict__ dinv,
                                                      const float* __restrict__ b_gcn,
                                                      const float* __restrict__ bn2w,
                                                      const float* __restrict__ bn2b,
                                                      const float* __restrict__ W_gate,
                                                      const float* __restrict__ b_gate,
                                                      float* __restrict__ out2,
                                                      float* __restrict__ gate, int N) {
    int n = (blockIdx.x * 256 + threadIdx.x) >> 5;
    if (n >= N) return;
    int lane = threadIdx.x & 31;
    int sub = lane & 7;
    int beg = offs[n], end = offs[n + 1];
    float dn = __ldg(dinv + n);

    uint2 us = __ldg((const uint2*)(h2 + n * 64 + lane * 2));
    float2 h0 = __half22float2(*(__half2*)&us.x);
    float2 h1 = __half22float2(*(__half2*)&us.y);
    float fs = dn * dn;
    float4 acc = make_float4(h0.x * fs, h0.y * fs, h1.x * fs, h1.y * fs);

    for (int c0 = beg; c0 < end; c0 += 8) {
        int e = c0 + sub;
        float f = 0.f; int s = 0;
        if (e < end) {
            s = __ldg(csr + e);
            f = __ldg(dinv + s) * dn;
        }
        #pragma unroll
        for (int i = 0; i < 8; i++) {
            int   si = __shfl_sync(0xffffffffu, s, i);
            float a  = __shfl_sync(0xffffffffu, f, i);
            uint2 u = __ldg((const uint2*)(h2 + si * 64 + lane * 2));
            float2 g0 = __half22float2(*(__half2*)&u.x);
            float2 g1 = __half22float2(*(__half2*)&u.y);
            acc.x += g0.x * a; acc.y += g0.y * a;
            acc.z += g1.x * a; acc.w += g1.y * a;
        }
    }

    int c = lane * 4;
    float4 bb = *(const float4*)(b_gcn + c);
    float4 w2 = *(const float4*)(bn2w + c);
    float4 b2 = *(const float4*)(bn2b + c);
    float4 v;
    v.x = elu_f(acc.x + bb.x) * w2.x + b2.x;
    v.y = elu_f(acc.y + bb.y) * w2.y + b2.y;
    v.z = elu_f(acc.z + bb.z) * w2.z + b2.z;
    v.w = elu_f(acc.w + bb.w) * w2.w + b2.w;
    *(float4*)(out2 + n * 128 + c) = v;

    float4 wg = *(const float4*)(W_gate + c);
    float p = v.x * wg.x + v.y * wg.y + v.z * wg.z + v.w * wg.w;
    #pragma unroll
    for (int o = 16; o; o >>= 1) p += __shfl_xor_sync(0xffffffffu, p, o);
    if (lane == 0) gate[n] = p + b_gate[0];
}

// ---------------- pooling + FC ----------------
__global__ __launch_bounds__(256) void pool_kernel(const float* __restrict__ out2,
                                                   const float* __restrict__ gate,
                                                   const int* __restrict__ gs,
                                                   const int* __restrict__ ge,
                                                   const float* __restrict__ W_fc,
                                                   const float* __restrict__ b_fc,
                                                   float* __restrict__ out) {
    int g = blockIdx.x;
    int start = gs[g], end = ge[g];
    int tid = threadIdx.x;
    __shared__ float red[256];
    __shared__ float wsh[256];

    float mx = -3.4e38f;
    for (int n = start + tid; n < end; n += 256) mx = fmaxf(mx, gate[n]);
    red[tid] = mx;
    __syncthreads();
    #pragma unroll
    for (int o = 128; o; o >>= 1) {
        if (tid < o) red[tid] = fmaxf(red[tid], red[tid + o]);
        __syncthreads();
    }
    float gmax = red[0];
    __syncthreads();

    int c = tid & 127, half = tid >> 7;
    float acc = 0.f, wloc = 0.f;
    for (int t0 = start; t0 < end; t0 += 256) {
        int tc = min(256, end - t0);
        if (tid < tc) {
            float wv = __expf(gate[t0 + tid] - gmax);
            wsh[tid] = wv;
            wloc += wv;
        }
        __syncthreads();
        for (int j = half; j < tc; j += 2)
            acc += wsh[j] * out2[(t0 + j) * 128 + c];
        __syncthreads();
    }

    red[tid] = wloc;
    __syncthreads();
    #pragma unroll
    for (int o = 128; o; o >>= 1) {
        if (tid < o) red[tid] += red[tid + o];
        __syncthreads();
    }
    float wsum = red[0];
    __syncthreads();

    red[tid] = acc;
    __syncthreads();
    float val = 0.f;
    if (tid < 128) val = (red[tid] + red[tid + 128]) / (wsum + 1e-16f) * W_fc[tid];
    __syncthreads();
    red[tid] = (tid < 128) ? val : 0.f;
    __syncthreads();
    #pragma unroll
    for (int o = 128; o; o >>= 1) {
        if (tid < o) red[tid] += red[tid + o];
        __syncthreads();
    }
    if (tid == 0) out[g] = red[0] + b_fc[0];
}

// ---------------- launch ----------------
extern "C" void kernel_launch(void* const* d_in, const int* in_sizes, int n_in,
                              void* d_out, int out_size) {
    const float* x       = (const float*)d_in[0];
    const int*   ei      = (const int*)d_in[1];
    const int*   batch   = (const int*)d_in[2];
    const float* W_gat   = (const float*)d_in[3];
    const float* att_src = (const float*)d_in[4];
    const float* att_dst = (const float*)d_in[5];
    const float* b_gat   = (const float*)d_in[6];
    const float* bn1w    = (const float*)d_in[7];
    const float* bn1b    = (const float*)d_in[8];
    const float* W_gcn   = (const float*)d_in[9];
    const float* b_gcn   = (const float*)d_in[10];
    const float* bn2w    = (const float*)d_in[11];
    const float* bn2b    = (const float*)d_in[12];
    const float* W_gate  = (const float*)d_in[13];
    const float* b_gate  = (const float*)d_in[14];
    const float* W_fc    = (const float*)d_in[15];
    const float* b_fc    = (const float*)d_in[16];
    float* out = (float*)d_out;

    int N = in_sizes[0] / 128;
    int E = in_sizes[1] / 2;
    int NB = (N + SCAN_B - 1) / SCAN_B;

    float *p_asrc, *p_adst, *p_out1, *p_out2, *p_gate, *p_dinv;
    __half2 *p_h, *p_h2;
    uint2 *p_wh1, *p_wl1, *p_wh2, *p_wl2;
    int *p_cnt, *p_offs, *p_cursor, *p_csr, *p_bsum, *p_boff, *p_gs, *p_ge;
    cudaGetSymbolAddress((void**)&p_h,     g_h);
    cudaGetSymbolAddress((void**)&p_h2,    g_h2);
    cudaGetSymbolAddress((void**)&p_asrc,  g_asrc);
    cudaGetSymbolAddress((void**)&p_adst,  g_adst);
    cudaGetSymbolAddress((void**)&p_out1,  g_out1);
    cudaGetSymbolAddress((void**)&p_out2,  g_out2);
    cudaGetSymbolAddress((void**)&p_gate,  g_gate);
    cudaGetSymbolAddress((void**)&p_dinv,  g_dinv);
    cudaGetSymbolAddress((void**)&p_cnt,   g_cnt);
    cudaGetSymbolAddress((void**)&p_offs,  g_offs);
    cudaGetSymbolAddress((void**)&p_cursor,g_cursor);
    cudaGetSymbolAddress((void**)&p_csr,   g_csr);
    cudaGetSymbolAddress((void**)&p_bsum,  g_bsum);
    cudaGetSymbolAddress((void**)&p_boff,  g_boff);
    cudaGetSymbolAddress((void**)&p_gs,    g_gstart);
    cudaGetSymbolAddress((void**)&p_ge,    g_gend);
    cudaGetSymbolAddress((void**)&p_wh1,   g_wh1);
    cudaGetSymbolAddress((void**)&p_wl1,   g_wl1);
    cudaGetSymbolAddress((void**)&p_wh2,   g_wh2);
    cudaGetSymbolAddress((void**)&p_wl2,   g_wl2);

    int gblk = (N + 63) / 64;

    init_kernel<<<(N + 255) / 256, 256>>>(p_cnt, p_gs, p_ge, batch, N);             // 0
    hist_kernel<<<(E + 255) / 256, 256>>>(ei, E, p_cnt);                            // 1
    wpack_kernel<<<32, 256>>>(W_gat, W_gcn, p_wh1, p_wl1, p_wh2, p_wl2);            // 2
    gemm_tc_kernel<true><<<gblk, 256>>>(x, p_wh1, p_wl1, p_h, att_src, att_dst,
                                        p_asrc, p_adst, N);                         // 3 (ncu)
    blocksum_kernel<<<NB, SCAN_B>>>(p_cnt, p_bsum, N);                              // 4
    bscan_kernel<<<1, 256>>>(p_bsum, p_boff, NB);                                   // 5
    scanfin_kernel<<<NB, SCAN_B>>>(p_cnt, p_boff, p_offs, p_cursor, N, E);          // 6
    scatter_kernel<<<(E + 255) / 256, 256>>>(ei, E, p_cursor, p_csr);               // 7
    gat_agg_kernel<<<(N * 32 + 255) / 256, 256>>>(p_csr, p_offs, p_h, p_asrc, p_adst,
                                                  b_gat, bn1w, bn1b, p_out1, p_dinv, N); // 8
    gemm_tc_kernel<false><<<gblk, 256>>>(p_out1, p_wh2, p_wl2, p_h2, nullptr, nullptr,
                                         nullptr, nullptr, N);                      // 9
    gcn_agg_kernel<<<(N * 32 + 255) / 256, 256>>>(p_csr, p_offs, p_h2, p_dinv,
                                                  b_gcn, bn2w, bn2b, W_gate, b_gate,
                                                  p_out2, p_gate, N);               // 10
    pool_kernel<<<64, 256>>>(p_out2, p_gate, p_gs, p_ge, W_fc, b_fc, out);          // 11
}